// round 1
// baseline (speedup 1.0000x reference)
#include <cuda_runtime.h>

#define B_     32
#define N_     577
#define L_     576
#define DIM_   512
#define HEADS_ 8
#define DH_    64
#define NDIM_  16
#define INNER_ 512
#define M_ROWS (B_ * N_)   // 18464

// -------- scratch (device globals: no allocations allowed) --------
__device__ float g_xm[(size_t)B_ * N_ * DIM_];        // xm = [cls ; ema_move(x[:,1:])]
__device__ float g_qk[(size_t)B_ * N_ * 2 * INNER_];  // [q | k] fused projection
__device__ float g_v [(size_t)B_ * N_ * INNER_];
__device__ float g_ao[(size_t)B_ * N_ * INNER_];      // attention output (pre W_out)
__device__ float g_cq[NDIM_][2 * DIM_];               // EMA decay q per (n, d2)
__device__ float g_cc[NDIM_][2 * DIM_];               // EMA coefficient c per (n, d2)

// ================= Stage 0: EMA coefficients =================
// p = sigmoid(delta); q = 1 - p*sigmoid(alpha); c = p*beta*gamma*sqrt(1/NDIM)
__global__ void coef_kernel(const float* __restrict__ delta, const float* __restrict__ alpha,
                            const float* __restrict__ beta,  const float* __restrict__ gamma) {
    int idx = blockIdx.x * blockDim.x + threadIdx.x;
    if (idx >= 2 * DIM_ * NDIM_) return;
    int d = idx / NDIM_;
    int n = idx % NDIM_;
    float p  = 1.f / (1.f + expf(-delta[idx]));
    float sa = 1.f / (1.f + expf(-alpha[idx]));
    float q  = 1.f - p * sa;
    float c  = p * beta[idx] * gamma[idx] * 0.25f;   // scale = sqrt(1/16)
    g_cq[n][d] = q;
    g_cc[n][d] = c;
}

// ================= Stage 1: bidirectional EMA scan =================
// One thread per (b, d). Forward scan writes partial y_f to g_xm, backward
// scan (same thread, no sync needed) adds y_b, applies silu(y + x*omega).
// cls row copied through unchanged.
__global__ void ema_kernel(const float* __restrict__ x, const float* __restrict__ omega) {
    int d = blockIdx.x * 128 + threadIdx.x;   // 0..511
    int b = blockIdx.y;
    const float* xb = x    + (size_t)b * N_ * DIM_;
    float*       yb = g_xm + (size_t)b * N_ * DIM_;

    yb[d] = xb[d];   // cls token passthrough

    float q1[NDIM_], c1[NDIM_], q2[NDIM_], c2[NDIM_], s[NDIM_];
#pragma unroll
    for (int n = 0; n < NDIM_; n++) {
        q1[n] = g_cq[n][d];         c1[n] = g_cc[n][d];
        q2[n] = g_cq[n][d + DIM_];  c2[n] = g_cc[n][d + DIM_];
        s[n] = 0.f;
    }
    // forward (causal, k1)
    for (int t = 0; t < L_; t++) {
        float xv = xb[(size_t)(t + 1) * DIM_ + d];
        float y = 0.f;
#pragma unroll
        for (int n = 0; n < NDIM_; n++) { s[n] = q1[n] * s[n] + xv; y += c1[n] * s[n]; }
        yb[(size_t)(t + 1) * DIM_ + d] = y;
    }
    float om = omega[d];
#pragma unroll
    for (int n = 0; n < NDIM_; n++) s[n] = 0.f;
    // backward (anticausal, k2) + combine + silu
    for (int t = L_ - 1; t >= 0; t--) {
        float xv = xb[(size_t)(t + 1) * DIM_ + d];
        float y  = yb[(size_t)(t + 1) * DIM_ + d];
#pragma unroll
        for (int n = 0; n < NDIM_; n++) { s[n] = q2[n] * s[n] + xv; y += c2[n] * s[n]; }
        float u = y + xv * om;
        yb[(size_t)(t + 1) * DIM_ + d] = u / (1.f + __expf(-u));   // silu
    }
}

// ================= SGEMM: 128x128 block tile, 8x8 per thread =================
// C[M,Nn] = A[M,K] @ B[K,Nn] (+ bias). Nn, K multiples of 128/8; M bounds-checked.
__device__ __forceinline__ void gemm_body(const float* __restrict__ A, const float* __restrict__ Bm,
                                          float* __restrict__ C, int M, int Nn, int K,
                                          const float* __restrict__ bias) {
    __shared__ float As[8][128];
    __shared__ float Bs[8][128];
    int tid = threadIdx.x;                 // 256 threads
    int bm = blockIdx.y * 128, bn = blockIdx.x * 128;
    int tx = tid % 16, ty = tid / 16;

    float acc[8][8];
#pragma unroll
    for (int i = 0; i < 8; i++)
#pragma unroll
        for (int j = 0; j < 8; j++) acc[i][j] = 0.f;

    int arow = tid / 2, acol = (tid % 2) * 4;    // A tile 128x8, float4/thread
    int brow = tid / 32, bcol = (tid % 32) * 4;  // B tile 8x128, float4/thread

    for (int k0 = 0; k0 < K; k0 += 8) {
        float4 av = make_float4(0.f, 0.f, 0.f, 0.f);
        if (bm + arow < M)
            av = *(const float4*)(A + (size_t)(bm + arow) * K + k0 + acol);
        As[acol + 0][arow] = av.x;
        As[acol + 1][arow] = av.y;
        As[acol + 2][arow] = av.z;
        As[acol + 3][arow] = av.w;
        float4 bv = *(const float4*)(Bm + (size_t)(k0 + brow) * Nn + bn + bcol);
        *(float4*)(&Bs[brow][bcol]) = bv;
        __syncthreads();
#pragma unroll
        for (int kk = 0; kk < 8; kk++) {
            float ra[8], rb[8];
#pragma unroll
            for (int i = 0; i < 8; i++) ra[i] = As[kk][ty * 8 + i];
#pragma unroll
            for (int j = 0; j < 8; j++) rb[j] = Bs[kk][tx * 8 + j];
#pragma unroll
            for (int i = 0; i < 8; i++)
#pragma unroll
                for (int j = 0; j < 8; j++) acc[i][j] += ra[i] * rb[j];
        }
        __syncthreads();
    }
#pragma unroll
    for (int i = 0; i < 8; i++) {
        int r = bm + ty * 8 + i;
        if (r >= M) break;
#pragma unroll
        for (int j4 = 0; j4 < 8; j4 += 4) {
            int c = bn + tx * 8 + j4;
            float4 v;
            v.x = acc[i][j4 + 0]; v.y = acc[i][j4 + 1];
            v.z = acc[i][j4 + 2]; v.w = acc[i][j4 + 3];
            if (bias) {
                v.x += bias[c + 0]; v.y += bias[c + 1];
                v.z += bias[c + 2]; v.w += bias[c + 3];
            }
            *(float4*)(C + (size_t)r * Nn + c) = v;
        }
    }
}

__global__ void gemm_qk(const float* __restrict__ W) {
    gemm_body(g_xm, W, g_qk, M_ROWS, 1024, 512, nullptr);
}
__global__ void gemm_v(const float* __restrict__ W) {
    gemm_body(g_xm, W, g_v, M_ROWS, 512, 512, nullptr);
}
__global__ void gemm_out(const float* __restrict__ W, const float* __restrict__ bias,
                         float* __restrict__ out) {
    gemm_body(g_ao, W, out, M_ROWS, 512, 512, bias);
}

// ================= Stage 3: attention =================
// out = softmax(QK^T * 0.125) @ V  +  bias @ V,  bias[i,j] = rel_bias[576 + j - i].
// Block: 256 threads = 8 warps, 4 query rows per warp (32 rows/CTA), j-tiles of 64.
// Online softmax for the first term; bias term needs no normalization.
__global__ void attn_kernel(const float* __restrict__ rb) {
    __shared__ float Ks[64][65];
    __shared__ float Vs[64][65];
    __shared__ float Qs[32][65];
    __shared__ float RBs[2 * N_ - 1];

    int b = blockIdx.z, h = blockIdx.y;
    int i0 = blockIdx.x * 32;
    int tid = threadIdx.x, lane = tid & 31, w = tid >> 5;

    const float* qbase = g_qk + (size_t)b * N_ * 1024 + h * 64;
    const float* kbase = qbase + 512;
    const float* vbase = g_v + (size_t)b * N_ * 512 + h * 64;

    for (int t = tid; t < 2 * N_ - 1; t += 256) RBs[t] = rb[t];
    for (int t = tid; t < 32 * 64; t += 256) {
        int r = t >> 6, dd = t & 63;
        int i = i0 + r;
        Qs[r][dd] = (i < N_) ? qbase[(size_t)i * 1024 + dd] : 0.f;
    }

    float m[4], Z[4], a0[4], a1[4], bb0[4], bb1[4];
#pragma unroll
    for (int r = 0; r < 4; r++) {
        m[r] = -1e30f; Z[r] = 0.f;
        a0[r] = a1[r] = bb0[r] = bb1[r] = 0.f;
    }
    __syncthreads();

    for (int j0 = 0; j0 < N_; j0 += 64) {
        for (int t = tid; t < 64 * 64; t += 256) {
            int jj = t >> 6, dd = t & 63;
            int j = j0 + jj;
            Ks[jj][dd] = (j < N_) ? kbase[(size_t)j * 1024 + dd] : 0.f;
            Vs[jj][dd] = (j < N_) ? vbase[(size_t)j * 512 + dd] : 0.f;
        }
        __syncthreads();
#pragma unroll
        for (int r = 0; r < 4; r++) {
            int row = w * 4 + r;
            int i = i0 + row;
            float s0 = 0.f, s1 = 0.f;
#pragma unroll
            for (int dd = 0; dd < 64; dd++) {
                float qv = Qs[row][dd];
                s0 += qv * Ks[lane][dd];
                s1 += qv * Ks[lane + 32][dd];
            }
            s0 *= 0.125f; s1 *= 0.125f;
            if (j0 + lane      >= N_) s0 = -1e30f;
            if (j0 + lane + 32 >= N_) s1 = -1e30f;
            float tmax = fmaxf(s0, s1);
#pragma unroll
            for (int o = 16; o > 0; o >>= 1)
                tmax = fmaxf(tmax, __shfl_xor_sync(0xffffffffu, tmax, o));
            float nm = fmaxf(m[r], tmax);
            float corr = __expf(m[r] - nm);
            a0[r] *= corr; a1[r] *= corr; Z[r] *= corr;
            float p0 = __expf(s0 - nm), p1 = __expf(s1 - nm);
            m[r] = nm;
            float zs = p0 + p1;
#pragma unroll
            for (int o = 16; o > 0; o >>= 1)
                zs += __shfl_xor_sync(0xffffffffu, zs, o);
            Z[r] += zs;
            // PV + bias*V accumulation
#pragma unroll 4
            for (int j = 0; j < 64; j++) {
                float pj = __shfl_sync(0xffffffffu, (j < 32) ? p0 : p1, j & 31);
                int jg = j0 + j;
                float bj = 0.f;
                if (jg < N_ && i < N_) bj = RBs[N_ - 1 + jg - i];
                float v0 = Vs[j][lane];
                float v1 = Vs[j][lane + 32];
                a0[r]  += pj * v0;  a1[r]  += pj * v1;
                bb0[r] += bj * v0;  bb1[r] += bj * v1;
            }
        }
        __syncthreads();
    }
#pragma unroll
    for (int r = 0; r < 4; r++) {
        int i = i0 + w * 4 + r;
        if (i < N_) {
            float invZ = 1.f / Z[r];
            float* o = g_ao + ((size_t)b * N_ + i) * 512 + h * 64;
            o[lane]      = a0[r] * invZ + bb0[r];
            o[lane + 32] = a1[r] * invZ + bb1[r];
        }
    }
}

// ================= launch =================
extern "C" void kernel_launch(void* const* d_in, const int* in_sizes, int n_in,
                              void* d_out, int out_size) {
    const float* x         = (const float*)d_in[0];
    const float* W_qk      = (const float*)d_in[1];
    const float* W_v       = (const float*)d_in[2];
    const float* W_out     = (const float*)d_in[3];
    const float* b_out     = (const float*)d_in[4];
    const float* rel_bias  = (const float*)d_in[5];
    const float* ema_delta = (const float*)d_in[6];
    const float* ema_alpha = (const float*)d_in[7];
    const float* ema_beta  = (const float*)d_in[8];
    const float* ema_gamma = (const float*)d_in[9];
    const float* ema_omega = (const float*)d_in[10];
    float* out = (float*)d_out;

    coef_kernel<<<(2 * DIM_ * NDIM_ + 255) / 256, 256>>>(ema_delta, ema_alpha, ema_beta, ema_gamma);
    ema_kernel<<<dim3(DIM_ / 128, B_), 128>>>(x, ema_omega);

    dim3 gqk(1024 / 128, (M_ROWS + 127) / 128);
    gemm_qk<<<gqk, 256>>>(W_qk);
    dim3 gv(512 / 128, (M_ROWS + 127) / 128);
    gemm_v<<<gv, 256>>>(W_v);

    attn_kernel<<<dim3((N_ + 31) / 32, HEADS_, B_), 256>>>(rel_bias);

    dim3 go(512 / 128, (M_ROWS + 127) / 128);
    gemm_out<<<go, 256>>>(W_out, b_out, out);
}

// round 2
// speedup vs baseline: 5.3531x; 5.3531x over previous
#include <cuda_runtime.h>

#define B_     32
#define N_     577
#define L_     576
#define DIM_   512
#define HEADS_ 8
#define DH_    64
#define NDIM_  16
#define INNER_ 512
#define M_ROWS (B_ * N_)   // 18464

// -------- scratch (device globals: no allocations allowed) --------
__device__ float g_xm[(size_t)B_ * N_ * DIM_];        // xm = [cls ; ema_move(x[:,1:])]
__device__ float g_qk[(size_t)B_ * N_ * 2 * INNER_];  // [q | k]
__device__ float g_v [(size_t)B_ * N_ * INNER_];
__device__ float g_ao[(size_t)B_ * N_ * INNER_];      // attention output (pre W_out)
__device__ float g_cq[NDIM_][2 * DIM_];
__device__ float g_cc[NDIM_][2 * DIM_];

// ---------------- tf32 helpers ----------------
__device__ __forceinline__ unsigned f2tf(float x) {
    unsigned u;
    asm("cvt.rna.tf32.f32 %0, %1;" : "=r"(u) : "f"(x));
    return u;
}
__device__ __forceinline__ float f2tff(float x) { return __uint_as_float(f2tf(x)); }

__device__ __forceinline__ void mma8(float* c, const unsigned* a, unsigned b0, unsigned b1) {
    asm volatile(
        "mma.sync.aligned.m16n8k8.row.col.f32.tf32.tf32.f32 "
        "{%0,%1,%2,%3},{%4,%5,%6,%7},{%8,%9},{%0,%1,%2,%3};"
        : "+f"(c[0]), "+f"(c[1]), "+f"(c[2]), "+f"(c[3])
        : "r"(a[0]), "r"(a[1]), "r"(a[2]), "r"(a[3]), "r"(b0), "r"(b1));
}

// ================= Stage 0: EMA coefficients =================
__global__ void coef_kernel(const float* __restrict__ delta, const float* __restrict__ alpha,
                            const float* __restrict__ beta,  const float* __restrict__ gamma) {
    int idx = blockIdx.x * blockDim.x + threadIdx.x;
    if (idx >= 2 * DIM_ * NDIM_) return;
    int d = idx / NDIM_;
    int n = idx % NDIM_;
    float p  = 1.f / (1.f + expf(-delta[idx]));
    float sa = 1.f / (1.f + expf(-alpha[idx]));
    g_cq[n][d] = 1.f - p * sa;
    g_cc[n][d] = p * beta[idx] * gamma[idx] * 0.25f;
}

// ================= Stage 1: bidirectional EMA scan =================
__global__ void ema_kernel(const float* __restrict__ x, const float* __restrict__ omega) {
    int d = blockIdx.x * 128 + threadIdx.x;
    int b = blockIdx.y;
    const float* xb = x    + (size_t)b * N_ * DIM_;
    float*       yb = g_xm + (size_t)b * N_ * DIM_;

    yb[d] = xb[d];   // cls token passthrough

    float q1[NDIM_], c1[NDIM_], q2[NDIM_], c2[NDIM_], s[NDIM_];
#pragma unroll
    for (int n = 0; n < NDIM_; n++) {
        q1[n] = g_cq[n][d];         c1[n] = g_cc[n][d];
        q2[n] = g_cq[n][d + DIM_];  c2[n] = g_cc[n][d + DIM_];
        s[n] = 0.f;
    }
    for (int t = 0; t < L_; t++) {
        float xv = xb[(size_t)(t + 1) * DIM_ + d];
        float y = 0.f;
#pragma unroll
        for (int n = 0; n < NDIM_; n++) { s[n] = q1[n] * s[n] + xv; y += c1[n] * s[n]; }
        yb[(size_t)(t + 1) * DIM_ + d] = y;
    }
    float om = omega[d];
#pragma unroll
    for (int n = 0; n < NDIM_; n++) s[n] = 0.f;
    for (int t = L_ - 1; t >= 0; t--) {
        float xv = xb[(size_t)(t + 1) * DIM_ + d];
        float y  = yb[(size_t)(t + 1) * DIM_ + d];
#pragma unroll
        for (int n = 0; n < NDIM_; n++) { s[n] = q2[n] * s[n] + xv; y += c2[n] * s[n]; }
        float u = y + xv * om;
        yb[(size_t)(t + 1) * DIM_ + d] = u / (1.f + __expf(-u));
    }
}

// ================= tf32 mma GEMM: 128x128 tile, 8 warps =================
// C[M,Nn] = A[M,512] @ B[512,Nn] (+bias). Nn multiple of 128, M guarded.
__device__ __forceinline__ void gemm_tc_body(const float* __restrict__ A, const float* __restrict__ Bm,
                                             float* __restrict__ C, int M, int Nn,
                                             const float* __restrict__ bias) {
    __shared__ float As[128][36];   // row-major, stride 36 (=4 mod 32)
    __shared__ float Bs[32][136];   // row-major, stride 136 (=8 mod 32)

    int tid = threadIdx.x, lane = tid & 31, w = tid >> 5;
    int gr = lane >> 2, tg = lane & 3;
    int wm = w & 1, wn = w >> 1;             // 2 x 4 warp grid -> 64x32 per warp
    int bm = blockIdx.y * 128, bn = blockIdx.x * 128;

    float acc[4][4][4];
#pragma unroll
    for (int mt = 0; mt < 4; mt++)
#pragma unroll
        for (int nt = 0; nt < 4; nt++)
#pragma unroll
            for (int e = 0; e < 4; e++) acc[mt][nt][e] = 0.f;

    for (int k0 = 0; k0 < 512; k0 += 32) {
#pragma unroll
        for (int it = 0; it < 4; it++) {
            int idx = tid + it * 256;          // A: 128 rows x 8 float4
            int row = idx >> 3, kq = (idx & 7) * 4;
            float4 v = make_float4(0.f, 0.f, 0.f, 0.f);
            if (bm + row < M) v = *(const float4*)(A + (size_t)(bm + row) * 512 + k0 + kq);
            As[row][kq + 0] = f2tff(v.x);
            As[row][kq + 1] = f2tff(v.y);
            As[row][kq + 2] = f2tff(v.z);
            As[row][kq + 3] = f2tff(v.w);

            int kr = idx >> 5, nq = (idx & 31) * 4;  // B: 32 rows x 32 float4
            float4 u = *(const float4*)(Bm + (size_t)(k0 + kr) * Nn + bn + nq);
            float4 ut = make_float4(f2tff(u.x), f2tff(u.y), f2tff(u.z), f2tff(u.w));
            *(float4*)(&Bs[kr][nq]) = ut;
        }
        __syncthreads();
#pragma unroll
        for (int kk = 0; kk < 4; kk++) {
            unsigned a[4][4];
#pragma unroll
            for (int mt = 0; mt < 4; mt++) {
                int r = wm * 64 + mt * 16 + gr;
                int c = kk * 8 + tg;
                a[mt][0] = __float_as_uint(As[r][c]);
                a[mt][1] = __float_as_uint(As[r + 8][c]);
                a[mt][2] = __float_as_uint(As[r][c + 4]);
                a[mt][3] = __float_as_uint(As[r + 8][c + 4]);
            }
#pragma unroll
            for (int nt = 0; nt < 4; nt++) {
                int col = wn * 32 + nt * 8 + gr;
                unsigned b0 = __float_as_uint(Bs[kk * 8 + tg][col]);
                unsigned b1 = __float_as_uint(Bs[kk * 8 + tg + 4][col]);
#pragma unroll
                for (int mt = 0; mt < 4; mt++) mma8(acc[mt][nt], a[mt], b0, b1);
            }
        }
        __syncthreads();
    }
#pragma unroll
    for (int mt = 0; mt < 4; mt++) {
        int r0 = bm + wm * 64 + mt * 16 + gr;
#pragma unroll
        for (int nt = 0; nt < 4; nt++) {
            int col = bn + wn * 32 + nt * 8 + 2 * tg;
            float bx = bias ? bias[col] : 0.f, by = bias ? bias[col + 1] : 0.f;
            if (r0 < M) {
                float2 v = make_float2(acc[mt][nt][0] + bx, acc[mt][nt][1] + by);
                *(float2*)(C + (size_t)r0 * Nn + col) = v;
            }
            if (r0 + 8 < M) {
                float2 v = make_float2(acc[mt][nt][2] + bx, acc[mt][nt][3] + by);
                *(float2*)(C + (size_t)(r0 + 8) * Nn + col) = v;
            }
        }
    }
}

__global__ void gemm_qk_tc(const float* __restrict__ W) {
    gemm_tc_body(g_xm, W, g_qk, M_ROWS, 1024, nullptr);
}
__global__ void gemm_v_tc(const float* __restrict__ W) {
    gemm_tc_body(g_xm, W, g_v, M_ROWS, 512, nullptr);
}
__global__ void gemm_out_tc(const float* __restrict__ W, const float* __restrict__ bias,
                            float* __restrict__ out) {
    gemm_tc_body(g_ao, W, out, M_ROWS, 512, bias);
}

// ================= Stage 3: flash attention with tf32 mma =================
// out = softmax(QK^T/8) @ V + bias @ V,  bias[i,j] = rel_bias[576 + j - i].
// CTA: 64 q-rows, 4 warps x 16 rows each, 128 threads; key tiles of 64.
#define ASTR 72
__global__ void flash_attn_tc(const float* __restrict__ rb) {
    extern __shared__ float sm[];
    float* Ks = sm;                  // [64][72]  row-major (j, d)
    float* Vs = sm + 64 * ASTR;      // [64][72]  row-major (j, d)
    float* Ps = sm + 128 * ASTR;     // [64][72]  row-major (i_local, j_local)

    int b = blockIdx.z, h = blockIdx.y;
    int i0 = blockIdx.x * 64;
    int tid = threadIdx.x, lane = tid & 31, w = tid >> 5;
    int gr = lane >> 2, tg = lane & 3;

    const float* qb = g_qk + (size_t)b * N_ * 1024 + h * 64;
    const float* kb = qb + 512;
    const float* vb = g_v + (size_t)b * N_ * 512 + h * 64;

    // Q fragments (A-operand), held in registers for all k-tiles. Scale by 1/8.
    unsigned qa[8][4];
    int rlo = i0 + w * 16 + gr;
    int rhi = rlo + 8;
#pragma unroll
    for (int kk = 0; kk < 8; kk++) {
        int c0 = kk * 8 + tg;
        float v0 = (rlo < N_) ? 0.125f * qb[(size_t)rlo * 1024 + c0]     : 0.f;
        float v1 = (rhi < N_) ? 0.125f * qb[(size_t)rhi * 1024 + c0]     : 0.f;
        float v2 = (rlo < N_) ? 0.125f * qb[(size_t)rlo * 1024 + c0 + 4] : 0.f;
        float v3 = (rhi < N_) ? 0.125f * qb[(size_t)rhi * 1024 + c0 + 4] : 0.f;
        qa[kk][0] = f2tf(v0); qa[kk][1] = f2tf(v1);
        qa[kk][2] = f2tf(v2); qa[kk][3] = f2tf(v3);
    }

    float o[8][4], ob[8][4];
#pragma unroll
    for (int nt = 0; nt < 8; nt++)
#pragma unroll
        for (int e = 0; e < 4; e++) { o[nt][e] = 0.f; ob[nt][e] = 0.f; }
    float mlo = -1e30f, mhi = -1e30f, zlo = 0.f, zhi = 0.f;

    for (int j0 = 0; j0 < N_; j0 += 64) {
        __syncthreads();
#pragma unroll
        for (int it = 0; it < 8; it++) {
            int idx = tid + it * 128;        // 64 rows x 16 float4
            int row = idx >> 4, cq = (idx & 15) * 4;
            int j = j0 + row;
            float4 kv = make_float4(0.f, 0.f, 0.f, 0.f);
            float4 vv = kv;
            if (j < N_) {
                kv = *(const float4*)(kb + (size_t)j * 1024 + cq);
                vv = *(const float4*)(vb + (size_t)j * 512 + cq);
            }
            float4 kt = make_float4(f2tff(kv.x), f2tff(kv.y), f2tff(kv.z), f2tff(kv.w));
            float4 vt = make_float4(f2tff(vv.x), f2tff(vv.y), f2tff(vv.z), f2tff(vv.w));
            *(float4*)(Ks + row * ASTR + cq) = kt;
            *(float4*)(Vs + row * ASTR + cq) = vt;
        }
        __syncthreads();

        // ---- S = Q @ K^T  (16 rows x 64 cols per warp) ----
        float s[8][4];
#pragma unroll
        for (int nt = 0; nt < 8; nt++) {
#pragma unroll
            for (int e = 0; e < 4; e++) s[nt][e] = 0.f;
#pragma unroll
            for (int kk = 0; kk < 8; kk++) {
                unsigned b0 = __float_as_uint(Ks[(nt * 8 + gr) * ASTR + kk * 8 + tg]);
                unsigned b1 = __float_as_uint(Ks[(nt * 8 + gr) * ASTR + kk * 8 + tg + 4]);
                mma8(s[nt], qa[kk], b0, b1);
            }
        }

        // ---- online softmax ----
        float tlo = -1e30f, thi = -1e30f;
#pragma unroll
        for (int nt = 0; nt < 8; nt++) {
            int col = j0 + nt * 8 + 2 * tg;
            if (col < N_)     { tlo = fmaxf(tlo, s[nt][0]); thi = fmaxf(thi, s[nt][2]); }
            if (col + 1 < N_) { tlo = fmaxf(tlo, s[nt][1]); thi = fmaxf(thi, s[nt][3]); }
        }
#pragma unroll
        for (int off = 1; off <= 2; off <<= 1) {
            tlo = fmaxf(tlo, __shfl_xor_sync(0xffffffffu, tlo, off));
            thi = fmaxf(thi, __shfl_xor_sync(0xffffffffu, thi, off));
        }
        float mlon = fmaxf(mlo, tlo), mhin = fmaxf(mhi, thi);
        float sclo = __expf(mlo - mlon), schi = __expf(mhi - mhin);
        float psl = 0.f, psh = 0.f;
        int prow_lo = (w * 16 + gr) * ASTR;
        int prow_hi = (w * 16 + gr + 8) * ASTR;
#pragma unroll
        for (int nt = 0; nt < 8; nt++) {
            int col = j0 + nt * 8 + 2 * tg;
            float p0 = (col     < N_) ? __expf(s[nt][0] - mlon) : 0.f;
            float p1 = (col + 1 < N_) ? __expf(s[nt][1] - mlon) : 0.f;
            float p2 = (col     < N_) ? __expf(s[nt][2] - mhin) : 0.f;
            float p3 = (col + 1 < N_) ? __expf(s[nt][3] - mhin) : 0.f;
            psl += p0 + p1; psh += p2 + p3;
            o[nt][0] *= sclo; o[nt][1] *= sclo;
            o[nt][2] *= schi; o[nt][3] *= schi;
            *(float2*)(Ps + prow_lo + nt * 8 + 2 * tg) = make_float2(f2tff(p0), f2tff(p1));
            *(float2*)(Ps + prow_hi + nt * 8 + 2 * tg) = make_float2(f2tff(p2), f2tff(p3));
        }
#pragma unroll
        for (int off = 1; off <= 2; off <<= 1) {
            psl += __shfl_xor_sync(0xffffffffu, psl, off);
            psh += __shfl_xor_sync(0xffffffffu, psh, off);
        }
        zlo = zlo * sclo + psl;  zhi = zhi * schi + psh;
        mlo = mlon;  mhi = mhin;
        __syncwarp();

        // ---- O += P @ V ;  Ob += bias @ V ----
#pragma unroll
        for (int kk = 0; kk < 8; kk++) {
            unsigned pa[4], ba[4];
            int pc = kk * 8 + tg;
            pa[0] = __float_as_uint(Ps[prow_lo + pc]);
            pa[1] = __float_as_uint(Ps[prow_hi + pc]);
            pa[2] = __float_as_uint(Ps[prow_lo + pc + 4]);
            pa[3] = __float_as_uint(Ps[prow_hi + pc + 4]);
            int jlo = j0 + kk * 8 + tg, jhi = jlo + 4;
            float b00 = (rlo < N_ && jlo < N_) ? rb[576 + jlo - rlo] : 0.f;
            float b01 = (rhi < N_ && jlo < N_) ? rb[576 + jlo - rhi] : 0.f;
            float b02 = (rlo < N_ && jhi < N_) ? rb[576 + jhi - rlo] : 0.f;
            float b03 = (rhi < N_ && jhi < N_) ? rb[576 + jhi - rhi] : 0.f;
            ba[0] = f2tf(b00); ba[1] = f2tf(b01); ba[2] = f2tf(b02); ba[3] = f2tf(b03);
#pragma unroll
            for (int nt = 0; nt < 8; nt++) {
                unsigned v0 = __float_as_uint(Vs[(kk * 8 + tg) * ASTR + nt * 8 + gr]);
                unsigned v1 = __float_as_uint(Vs[(kk * 8 + tg + 4) * ASTR + nt * 8 + gr]);
                mma8(o[nt],  pa, v0, v1);
                mma8(ob[nt], ba, v0, v1);
            }
        }
        __syncwarp();
    }

    // ---- epilogue: O/Z + Ob ----
    float izlo = 1.f / zlo, izhi = 1.f / zhi;
#pragma unroll
    for (int nt = 0; nt < 8; nt++) {
        int col = h * 64 + nt * 8 + 2 * tg;
        if (rlo < N_) {
            float2 v = make_float2(o[nt][0] * izlo + ob[nt][0],
                                   o[nt][1] * izlo + ob[nt][1]);
            *(float2*)(g_ao + ((size_t)b * N_ + rlo) * 512 + col) = v;
        }
        if (rhi < N_) {
            float2 v = make_float2(o[nt][2] * izhi + ob[nt][2],
                                   o[nt][3] * izhi + ob[nt][3]);
            *(float2*)(g_ao + ((size_t)b * N_ + rhi) * 512 + col) = v;
        }
    }
}

// ================= launch =================
extern "C" void kernel_launch(void* const* d_in, const int* in_sizes, int n_in,
                              void* d_out, int out_size) {
    const float* x         = (const float*)d_in[0];
    const float* W_qk      = (const float*)d_in[1];
    const float* W_v       = (const float*)d_in[2];
    const float* W_out     = (const float*)d_in[3];
    const float* b_out     = (const float*)d_in[4];
    const float* rel_bias  = (const float*)d_in[5];
    const float* ema_delta = (const float*)d_in[6];
    const float* ema_alpha = (const float*)d_in[7];
    const float* ema_beta  = (const float*)d_in[8];
    const float* ema_gamma = (const float*)d_in[9];
    const float* ema_omega = (const float*)d_in[10];
    float* out = (float*)d_out;

    coef_kernel<<<(2 * DIM_ * NDIM_ + 255) / 256, 256>>>(ema_delta, ema_alpha, ema_beta, ema_gamma);
    ema_kernel<<<dim3(DIM_ / 128, B_), 128>>>(x, ema_omega);

    gemm_qk_tc<<<dim3(8, 145), 256>>>(W_qk);
    gemm_v_tc<<<dim3(4, 145), 256>>>(W_v);

    static int smem_set = 0;
    if (!smem_set) {
        cudaFuncSetAttribute(flash_attn_tc, cudaFuncAttributeMaxDynamicSharedMemorySize,
                             3 * 64 * ASTR * (int)sizeof(float));
        smem_set = 1;
    }
    flash_attn_tc<<<dim3(10, HEADS_, B_), 128, 3 * 64 * ASTR * sizeof(float)>>>(rel_bias);

    gemm_out_tc<<<dim3(4, 145), 256>>>(W_out, b_out, out);
}

// round 3
// speedup vs baseline: 8.0707x; 1.5077x over previous
#include <cuda_runtime.h>

#define B_     32
#define N_     577
#define L_     576
#define DIM_   512
#define HEADS_ 8
#define DH_    64
#define NDIM_  16
#define INNER_ 512
#define M_ROWS (B_ * N_)   // 18464

// -------- scratch (device globals: no allocations allowed) --------
__device__ float g_xm[(size_t)B_ * N_ * DIM_];
__device__ float g_qk[(size_t)B_ * N_ * 2 * INNER_];
__device__ float g_v [(size_t)B_ * N_ * INNER_];
__device__ float g_ao[(size_t)B_ * N_ * INNER_];
__device__ float g_cq[NDIM_][2 * DIM_];
__device__ float g_cc[NDIM_][2 * DIM_];

// ---------------- tf32 helpers ----------------
__device__ __forceinline__ unsigned f2tf(float x) {
    unsigned u;
    asm("cvt.rna.tf32.f32 %0, %1;" : "=r"(u) : "f"(x));
    return u;
}
__device__ __forceinline__ float f2tff(float x) { return __uint_as_float(f2tf(x)); }

__device__ __forceinline__ void mma8(float* c, const unsigned* a, unsigned b0, unsigned b1) {
    asm volatile(
        "mma.sync.aligned.m16n8k8.row.col.f32.tf32.tf32.f32 "
        "{%0,%1,%2,%3},{%4,%5,%6,%7},{%8,%9},{%0,%1,%2,%3};"
        : "+f"(c[0]), "+f"(c[1]), "+f"(c[2]), "+f"(c[3])
        : "r"(a[0]), "r"(a[1]), "r"(a[2]), "r"(a[3]), "r"(b0), "r"(b1));
}

// ================= Stage 0: EMA coefficients =================
__global__ void coef_kernel(const float* __restrict__ delta, const float* __restrict__ alpha,
                            const float* __restrict__ beta,  const float* __restrict__ gamma) {
    int idx = blockIdx.x * blockDim.x + threadIdx.x;
    if (idx >= 2 * DIM_ * NDIM_) return;
    int d = idx / NDIM_;
    int n = idx % NDIM_;
    float p  = 1.f / (1.f + expf(-delta[idx]));
    float sa = 1.f / (1.f + expf(-alpha[idx]));
    g_cq[n][d] = 1.f - p * sa;
    g_cc[n][d] = p * beta[idx] * gamma[idx] * 0.25f;
}

// ================= Stage 1: bidirectional EMA scan =================
__global__ void ema_kernel(const float* __restrict__ x, const float* __restrict__ omega) {
    int d = blockIdx.x * 128 + threadIdx.x;
    int b = blockIdx.y;
    const float* xb = x    + (size_t)b * N_ * DIM_;
    float*       yb = g_xm + (size_t)b * N_ * DIM_;

    yb[d] = xb[d];   // cls token passthrough

    float q1[NDIM_], c1[NDIM_], q2[NDIM_], c2[NDIM_], s[NDIM_];
#pragma unroll
    for (int n = 0; n < NDIM_; n++) {
        q1[n] = g_cq[n][d];         c1[n] = g_cc[n][d];
        q2[n] = g_cq[n][d + DIM_];  c2[n] = g_cc[n][d + DIM_];
        s[n] = 0.f;
    }
    for (int t = 0; t < L_; t++) {
        float xv = xb[(size_t)(t + 1) * DIM_ + d];
        float y = 0.f;
#pragma unroll
        for (int n = 0; n < NDIM_; n++) { s[n] = q1[n] * s[n] + xv; y += c1[n] * s[n]; }
        yb[(size_t)(t + 1) * DIM_ + d] = y;
    }
    float om = omega[d];
#pragma unroll
    for (int n = 0; n < NDIM_; n++) s[n] = 0.f;
    for (int t = L_ - 1; t >= 0; t--) {
        float xv = xb[(size_t)(t + 1) * DIM_ + d];
        float y  = yb[(size_t)(t + 1) * DIM_ + d];
#pragma unroll
        for (int n = 0; n < NDIM_; n++) { s[n] = q2[n] * s[n] + xv; y += c2[n] * s[n]; }
        float u = y + xv * om;
        yb[(size_t)(t + 1) * DIM_ + d] = u / (1.f + __expf(-u));
    }
}

// ================= tf32 mma GEMM: 128x128 tile, 8 warps =================
__device__ __forceinline__ void gemm_tc_body(const float* __restrict__ A, const float* __restrict__ Bm,
                                             float* __restrict__ C, int M, int Nn,
                                             const float* __restrict__ bias, int bnb) {
    __shared__ float As[128][36];   // stride 36 (=4 mod 32) -> A-frag conflict-free
    __shared__ float Bs[32][136];   // stride 136 (=8 mod 32) -> B-frag conflict-free

    int tid = threadIdx.x, lane = tid & 31, w = tid >> 5;
    int gr = lane >> 2, tg = lane & 3;
    int wm = w & 1, wn = w >> 1;
    int bm = blockIdx.y * 128, bn = bnb * 128;

    float acc[4][4][4];
#pragma unroll
    for (int mt = 0; mt < 4; mt++)
#pragma unroll
        for (int nt = 0; nt < 4; nt++)
#pragma unroll
            for (int e = 0; e < 4; e++) acc[mt][nt][e] = 0.f;

    for (int k0 = 0; k0 < 512; k0 += 32) {
#pragma unroll
        for (int it = 0; it < 4; it++) {
            int idx = tid + it * 256;
            int row = idx >> 3, kq = (idx & 7) * 4;
            float4 v = make_float4(0.f, 0.f, 0.f, 0.f);
            if (bm + row < M) v = *(const float4*)(A + (size_t)(bm + row) * 512 + k0 + kq);
            As[row][kq + 0] = f2tff(v.x);
            As[row][kq + 1] = f2tff(v.y);
            As[row][kq + 2] = f2tff(v.z);
            As[row][kq + 3] = f2tff(v.w);

            int kr = idx >> 5, nq = (idx & 31) * 4;
            float4 u = *(const float4*)(Bm + (size_t)(k0 + kr) * Nn + bn + nq);
            float4 ut = make_float4(f2tff(u.x), f2tff(u.y), f2tff(u.z), f2tff(u.w));
            *(float4*)(&Bs[kr][nq]) = ut;
        }
        __syncthreads();
#pragma unroll
        for (int kk = 0; kk < 4; kk++) {
            unsigned a[4][4];
#pragma unroll
            for (int mt = 0; mt < 4; mt++) {
                int r = wm * 64 + mt * 16 + gr;
                int c = kk * 8 + tg;
                a[mt][0] = __float_as_uint(As[r][c]);
                a[mt][1] = __float_as_uint(As[r + 8][c]);
                a[mt][2] = __float_as_uint(As[r][c + 4]);
                a[mt][3] = __float_as_uint(As[r + 8][c + 4]);
            }
#pragma unroll
            for (int nt = 0; nt < 4; nt++) {
                int col = wn * 32 + nt * 8 + gr;
                unsigned b0 = __float_as_uint(Bs[kk * 8 + tg][col]);
                unsigned b1 = __float_as_uint(Bs[kk * 8 + tg + 4][col]);
#pragma unroll
                for (int mt = 0; mt < 4; mt++) mma8(acc[mt][nt], a[mt], b0, b1);
            }
        }
        __syncthreads();
    }
#pragma unroll
    for (int mt = 0; mt < 4; mt++) {
        int r0 = bm + wm * 64 + mt * 16 + gr;
#pragma unroll
        for (int nt = 0; nt < 4; nt++) {
            int col = bn + wn * 32 + nt * 8 + 2 * tg;
            float bx = bias ? bias[col] : 0.f, by = bias ? bias[col + 1] : 0.f;
            if (r0 < M) {
                float2 v = make_float2(acc[mt][nt][0] + bx, acc[mt][nt][1] + by);
                *(float2*)(C + (size_t)r0 * Nn + col) = v;
            }
            if (r0 + 8 < M) {
                float2 v = make_float2(acc[mt][nt][2] + bx, acc[mt][nt][3] + by);
                *(float2*)(C + (size_t)(r0 + 8) * Nn + col) = v;
            }
        }
    }
}

// qk (8 n-blocks) and v (4 n-blocks) fused: one grid, shared A-tile working set.
__global__ void gemm_qkv_tc(const float* __restrict__ Wqk, const float* __restrict__ Wv) {
    if (blockIdx.x < 8)
        gemm_tc_body(g_xm, Wqk, g_qk, M_ROWS, 1024, nullptr, blockIdx.x);
    else
        gemm_tc_body(g_xm, Wv, g_v, M_ROWS, 512, nullptr, blockIdx.x - 8);
}
__global__ void gemm_out_tc(const float* __restrict__ W, const float* __restrict__ bias,
                            float* __restrict__ out) {
    gemm_tc_body(g_ao, W, out, M_ROWS, 512, bias, blockIdx.x);
}

// ================= Stage 3: flash attention with tf32 mma =================
// Strides chosen for conflict-free fragment loads:
//   Ks stride 68 (=4 mod 32): S B-frag bank = 4*gr+tg, all-distinct
//   Ps stride 68:             P A-frag bank = 4*gr+tg, all-distinct
//   Vs stride 72 (=8 mod 32): V B-frag bank = 8*tg+gr, all-distinct
#define KSTR 68
#define VSTR 72
#define PSTR 68
#define SMEM_FL (64 * KSTR + 64 * VSTR + 64 * PSTR + (2 * N_ - 1))

__global__ void __launch_bounds__(128, 3) flash_attn_tc(const float* __restrict__ rb) {
    extern __shared__ float sm[];
    float* Ks  = sm;                       // [64][KSTR]
    float* Vs  = Ks + 64 * KSTR;           // [64][VSTR]
    float* Ps  = Vs + 64 * VSTR;           // [64][PSTR]
    float* RBs = Ps + 64 * PSTR;           // [1153]

    int b = blockIdx.z, h = blockIdx.y;
    int i0 = blockIdx.x * 64;
    int tid = threadIdx.x, lane = tid & 31, w = tid >> 5;
    int gr = lane >> 2, tg = lane & 3;

    const float* qb = g_qk + (size_t)b * N_ * 1024 + h * 64;
    const float* kb = qb + 512;
    const float* vb = g_v + (size_t)b * N_ * 512 + h * 64;

    for (int t = tid; t < 2 * N_ - 1; t += 128) RBs[t] = rb[t];

    // Q fragments in registers for the whole k-loop; pre-scaled by 1/8.
    unsigned qa[8][4];
    int rlo = i0 + w * 16 + gr;
    int rhi = rlo + 8;
#pragma unroll
    for (int kk = 0; kk < 8; kk++) {
        int c0 = kk * 8 + tg;
        float v0 = (rlo < N_) ? 0.125f * qb[(size_t)rlo * 1024 + c0]     : 0.f;
        float v1 = (rhi < N_) ? 0.125f * qb[(size_t)rhi * 1024 + c0]     : 0.f;
        float v2 = (rlo < N_) ? 0.125f * qb[(size_t)rlo * 1024 + c0 + 4] : 0.f;
        float v3 = (rhi < N_) ? 0.125f * qb[(size_t)rhi * 1024 + c0 + 4] : 0.f;
        qa[kk][0] = f2tf(v0); qa[kk][1] = f2tf(v1);
        qa[kk][2] = f2tf(v2); qa[kk][3] = f2tf(v3);
    }

    float o[8][4], ob[8][4];
#pragma unroll
    for (int nt = 0; nt < 8; nt++)
#pragma unroll
        for (int e = 0; e < 4; e++) { o[nt][e] = 0.f; ob[nt][e] = 0.f; }
    float mlo = -1e30f, mhi = -1e30f, zlo = 0.f, zhi = 0.f;

    for (int j0 = 0; j0 < N_; j0 += 64) {
        bool full = (j0 + 64 <= N_);
        __syncthreads();
        if (full) {
#pragma unroll
            for (int it = 0; it < 8; it++) {
                int idx = tid + it * 128;
                int row = idx >> 4, cq = (idx & 15) * 4;
                int j = j0 + row;
                float4 kv = *(const float4*)(kb + (size_t)j * 1024 + cq);
                float4 vv = *(const float4*)(vb + (size_t)j * 512 + cq);
                float4 kt = make_float4(f2tff(kv.x), f2tff(kv.y), f2tff(kv.z), f2tff(kv.w));
                float4 vt = make_float4(f2tff(vv.x), f2tff(vv.y), f2tff(vv.z), f2tff(vv.w));
                *(float4*)(Ks + row * KSTR + cq) = kt;
                *(float4*)(Vs + row * VSTR + cq) = vt;
            }
        } else {
#pragma unroll
            for (int it = 0; it < 8; it++) {
                int idx = tid + it * 128;
                int row = idx >> 4, cq = (idx & 15) * 4;
                int j = j0 + row;
                float4 kv = make_float4(0.f, 0.f, 0.f, 0.f);
                float4 vv = kv;
                if (j < N_) {
                    kv = *(const float4*)(kb + (size_t)j * 1024 + cq);
                    vv = *(const float4*)(vb + (size_t)j * 512 + cq);
                }
                float4 kt = make_float4(f2tff(kv.x), f2tff(kv.y), f2tff(kv.z), f2tff(kv.w));
                float4 vt = make_float4(f2tff(vv.x), f2tff(vv.y), f2tff(vv.z), f2tff(vv.w));
                *(float4*)(Ks + row * KSTR + cq) = kt;
                *(float4*)(Vs + row * VSTR + cq) = vt;
            }
        }
        __syncthreads();

        // ---- S = Q @ K^T ----
        float s[8][4];
#pragma unroll
        for (int nt = 0; nt < 8; nt++) {
#pragma unroll
            for (int e = 0; e < 4; e++) s[nt][e] = 0.f;
#pragma unroll
            for (int kk = 0; kk < 8; kk++) {
                unsigned b0 = __float_as_uint(Ks[(nt * 8 + gr) * KSTR + kk * 8 + tg]);
                unsigned b1 = __float_as_uint(Ks[(nt * 8 + gr) * KSTR + kk * 8 + tg + 4]);
                mma8(s[nt], qa[kk], b0, b1);
            }
        }

        // ---- online softmax ----
        float tlo = -1e30f, thi = -1e30f;
#pragma unroll
        for (int nt = 0; nt < 8; nt++) {
            int col = j0 + nt * 8 + 2 * tg;
            if (full || col < N_)     { tlo = fmaxf(tlo, s[nt][0]); thi = fmaxf(thi, s[nt][2]); }
            if (full || col + 1 < N_) { tlo = fmaxf(tlo, s[nt][1]); thi = fmaxf(thi, s[nt][3]); }
        }
#pragma unroll
        for (int off = 1; off <= 2; off <<= 1) {
            tlo = fmaxf(tlo, __shfl_xor_sync(0xffffffffu, tlo, off));
            thi = fmaxf(thi, __shfl_xor_sync(0xffffffffu, thi, off));
        }
        float mlon = fmaxf(mlo, tlo), mhin = fmaxf(mhi, thi);
        float sclo = __expf(mlo - mlon), schi = __expf(mhi - mhin);
        float psl = 0.f, psh = 0.f;
        int prow_lo = (w * 16 + gr) * PSTR;
        int prow_hi = (w * 16 + gr + 8) * PSTR;
#pragma unroll
        for (int nt = 0; nt < 8; nt++) {
            int col = j0 + nt * 8 + 2 * tg;
            float p0 = (full || col     < N_) ? __expf(s[nt][0] - mlon) : 0.f;
            float p1 = (full || col + 1 < N_) ? __expf(s[nt][1] - mlon) : 0.f;
            float p2 = (full || col     < N_) ? __expf(s[nt][2] - mhin) : 0.f;
            float p3 = (full || col + 1 < N_) ? __expf(s[nt][3] - mhin) : 0.f;
            psl += p0 + p1; psh += p2 + p3;
            o[nt][0] *= sclo; o[nt][1] *= sclo;
            o[nt][2] *= schi; o[nt][3] *= schi;
            *(float2*)(Ps + prow_lo + nt * 8 + 2 * tg) = make_float2(f2tff(p0), f2tff(p1));
            *(float2*)(Ps + prow_hi + nt * 8 + 2 * tg) = make_float2(f2tff(p2), f2tff(p3));
        }
#pragma unroll
        for (int off = 1; off <= 2; off <<= 1) {
            psl += __shfl_xor_sync(0xffffffffu, psl, off);
            psh += __shfl_xor_sync(0xffffffffu, psh, off);
        }
        zlo = zlo * sclo + psl;  zhi = zhi * schi + psh;
        mlo = mlon;  mhi = mhin;
        __syncwarp();

        // ---- O += P @ V ;  Ob += bias @ V (bias from smem RBs) ----
#pragma unroll
        for (int kk = 0; kk < 8; kk++) {
            unsigned pa[4], ba[4];
            int pc = kk * 8 + tg;
            pa[0] = __float_as_uint(Ps[prow_lo + pc]);
            pa[1] = __float_as_uint(Ps[prow_hi + pc]);
            pa[2] = __float_as_uint(Ps[prow_lo + pc + 4]);
            pa[3] = __float_as_uint(Ps[prow_hi + pc + 4]);
            int jlo = j0 + kk * 8 + tg, jhi = jlo + 4;
            float b00 = (rlo < N_ && jlo < N_) ? RBs[576 + jlo - rlo] : 0.f;
            float b01 = (rhi < N_ && jlo < N_) ? RBs[576 + jlo - rhi] : 0.f;
            float b02 = (rlo < N_ && jhi < N_) ? RBs[576 + jhi - rlo] : 0.f;
            float b03 = (rhi < N_ && jhi < N_) ? RBs[576 + jhi - rhi] : 0.f;
            ba[0] = f2tf(b00); ba[1] = f2tf(b01); ba[2] = f2tf(b02); ba[3] = f2tf(b03);
#pragma unroll
            for (int nt = 0; nt < 8; nt++) {
                unsigned v0 = __float_as_uint(Vs[(kk * 8 + tg) * VSTR + nt * 8 + gr]);
                unsigned v1 = __float_as_uint(Vs[(kk * 8 + tg + 4) * VSTR + nt * 8 + gr]);
                mma8(o[nt],  pa, v0, v1);
                mma8(ob[nt], ba, v0, v1);
            }
        }
        __syncwarp();
    }

    // ---- epilogue: O/Z + Ob ----
    float izlo = 1.f / zlo, izhi = 1.f / zhi;
#pragma unroll
    for (int nt = 0; nt < 8; nt++) {
        int col = h * 64 + nt * 8 + 2 * tg;
        if (rlo < N_) {
            float2 v = make_float2(o[nt][0] * izlo + ob[nt][0],
                                   o[nt][1] * izlo + ob[nt][1]);
            *(float2*)(g_ao + ((size_t)b * N_ + rlo) * 512 + col) = v;
        }
        if (rhi < N_) {
            float2 v = make_float2(o[nt][2] * izhi + ob[nt][2],
                                   o[nt][3] * izhi + ob[nt][3]);
            *(float2*)(g_ao + ((size_t)b * N_ + rhi) * 512 + col) = v;
        }
    }
}

// ================= launch =================
extern "C" void kernel_launch(void* const* d_in, const int* in_sizes, int n_in,
                              void* d_out, int out_size) {
    const float* x         = (const float*)d_in[0];
    const float* W_qk      = (const float*)d_in[1];
    const float* W_v       = (const float*)d_in[2];
    const float* W_out     = (const float*)d_in[3];
    const float* b_out     = (const float*)d_in[4];
    const float* rel_bias  = (const float*)d_in[5];
    const float* ema_delta = (const float*)d_in[6];
    const float* ema_alpha = (const float*)d_in[7];
    const float* ema_beta  = (const float*)d_in[8];
    const float* ema_gamma = (const float*)d_in[9];
    const float* ema_omega = (const float*)d_in[10];
    float* out = (float*)d_out;

    coef_kernel<<<(2 * DIM_ * NDIM_ + 255) / 256, 256>>>(ema_delta, ema_alpha, ema_beta, ema_gamma);
    ema_kernel<<<dim3(DIM_ / 128, B_), 128>>>(x, ema_omega);

    gemm_qkv_tc<<<dim3(12, 145), 256>>>(W_qk, W_v);

    static int smem_set = 0;
    if (!smem_set) {
        cudaFuncSetAttribute(flash_attn_tc, cudaFuncAttributeMaxDynamicSharedMemorySize,
                             SMEM_FL * (int)sizeof(float));
        smem_set = 1;
    }
    flash_attn_tc<<<dim3(10, HEADS_, B_), 128, SMEM_FL * sizeof(float)>>>(rel_bias);

    gemm_out_tc<<<dim3(4, 145), 256>>>(W_out, b_out, out);
}

// round 4
// speedup vs baseline: 8.5315x; 1.0571x over previous
#include <cuda_runtime.h>

#define B_     32
#define N_     577
#define L_     576
#define DIM_   512
#define HEADS_ 8
#define DH_    64
#define NDIM_  16
#define INNER_ 512
#define M_ROWS (B_ * N_)   // 18464
#define CH_    8           // EMA chunks
#define CL_    72          // EMA chunk length (8*72 = 576)

// -------- scratch (device globals: no allocations allowed) --------
__device__ float g_xm[(size_t)B_ * N_ * DIM_];
__device__ float g_qk[(size_t)B_ * N_ * 2 * INNER_];
__device__ float g_v [(size_t)B_ * N_ * INNER_];
__device__ float g_ao[(size_t)B_ * N_ * INNER_];
__device__ float g_cq[NDIM_][2 * DIM_];
__device__ float g_cc[NDIM_][2 * DIM_];
__device__ float g_sf[(size_t)B_ * CH_ * NDIM_ * DIM_];   // fwd chunk-end states
__device__ float g_sb[(size_t)B_ * CH_ * NDIM_ * DIM_];   // bwd chunk-end states

// ---------------- tf32 helpers ----------------
__device__ __forceinline__ unsigned f2tf(float x) {
    unsigned u;
    asm("cvt.rna.tf32.f32 %0, %1;" : "=r"(u) : "f"(x));
    return u;
}
__device__ __forceinline__ float f2tff(float x) { return __uint_as_float(f2tf(x)); }

__device__ __forceinline__ void mma8(float* c, const unsigned* a, unsigned b0, unsigned b1) {
    asm volatile(
        "mma.sync.aligned.m16n8k8.row.col.f32.tf32.tf32.f32 "
        "{%0,%1,%2,%3},{%4,%5,%6,%7},{%8,%9},{%0,%1,%2,%3};"
        : "+f"(c[0]), "+f"(c[1]), "+f"(c[2]), "+f"(c[3])
        : "r"(a[0]), "r"(a[1]), "r"(a[2]), "r"(a[3]), "r"(b0), "r"(b1));
}

// ================= Stage 0: EMA coefficients =================
__global__ void coef_kernel(const float* __restrict__ delta, const float* __restrict__ alpha,
                            const float* __restrict__ beta,  const float* __restrict__ gamma) {
    int idx = blockIdx.x * blockDim.x + threadIdx.x;
    if (idx >= 2 * DIM_ * NDIM_) return;
    int d = idx / NDIM_;
    int n = idx % NDIM_;
    float p  = 1.f / (1.f + expf(-delta[idx]));
    float sa = 1.f / (1.f + expf(-alpha[idx]));
    g_cq[n][d] = 1.f - p * sa;
    g_cc[n][d] = p * beta[idx] * gamma[idx] * 0.25f;
}

// ================= Stage 1a: chunk-local EMA scans =================
// thread = (b, d, chunk c). Forward local partial -> g_xm; backward local
// partial added; chunk-end states to g_sf / g_sb.
__global__ void ema1_kernel(const float* __restrict__ x) {
    int d = blockIdx.x * 128 + threadIdx.x;
    int c = blockIdx.y, b = blockIdx.z;
    const float* xb = x    + (size_t)b * N_ * DIM_;
    float*       yb = g_xm + (size_t)b * N_ * DIM_;
    if (c == 0) yb[d] = xb[d];   // cls passthrough

    float q1[NDIM_], c1[NDIM_], q2[NDIM_], c2[NDIM_], s[NDIM_];
#pragma unroll
    for (int n = 0; n < NDIM_; n++) {
        q1[n] = g_cq[n][d];         c1[n] = g_cc[n][d];
        q2[n] = g_cq[n][d + DIM_];  c2[n] = g_cc[n][d + DIM_];
        s[n] = 0.f;
    }
    int t0 = c * CL_;
    for (int tl = 0; tl < CL_; tl++) {
        size_t idx = (size_t)(t0 + tl + 1) * DIM_ + d;
        float xv = xb[idx];
        float y = 0.f;
#pragma unroll
        for (int n = 0; n < NDIM_; n++) { s[n] = q1[n] * s[n] + xv; y += c1[n] * s[n]; }
        yb[idx] = y;
    }
#pragma unroll
    for (int n = 0; n < NDIM_; n++) {
        g_sf[(((size_t)b * CH_ + c) * NDIM_ + n) * DIM_ + d] = s[n];
        s[n] = 0.f;
    }
    for (int tl = CL_ - 1; tl >= 0; tl--) {
        size_t idx = (size_t)(t0 + tl + 1) * DIM_ + d;
        float xv = xb[idx];
        float y = yb[idx];
#pragma unroll
        for (int n = 0; n < NDIM_; n++) { s[n] = q2[n] * s[n] + xv; y += c2[n] * s[n]; }
        yb[idx] = y;
    }
#pragma unroll
    for (int n = 0; n < NDIM_; n++)
        g_sb[(((size_t)b * CH_ + c) * NDIM_ + n) * DIM_ + d] = s[n];
}

// ================= Stage 1b: cross-chunk corrections + silu =================
__device__ __forceinline__ float pow72f(float q) {
    float q2 = q * q, q4 = q2 * q2, q8 = q4 * q4;
    float q9 = q8 * q, q18 = q9 * q9, q36 = q18 * q18;
    return q36 * q36;
}
__global__ void ema2_kernel(const float* __restrict__ x, const float* __restrict__ omega) {
    int d = blockIdx.x * 128 + threadIdx.x;
    int c = blockIdx.y, b = blockIdx.z;
    const float* xb = x    + (size_t)b * N_ * DIM_;
    float*       yb = g_xm + (size_t)b * N_ * DIM_;

    float q1[NDIM_], c1[NDIM_], q2[NDIM_], c2[NDIM_];
#pragma unroll
    for (int n = 0; n < NDIM_; n++) {
        q1[n] = g_cq[n][d];         c1[n] = g_cc[n][d];
        q2[n] = g_cq[n][d + DIM_];  c2[n] = g_cc[n][d + DIM_];
    }
    // incoming states (sequential over <=7 chunks, 16-wide)
    float Sf[NDIM_], Sb[NDIM_];
#pragma unroll
    for (int n = 0; n < NDIM_; n++) { Sf[n] = 0.f; Sb[n] = 0.f; }
    for (int cp = 0; cp < c; cp++) {
#pragma unroll
        for (int n = 0; n < NDIM_; n++) {
            float q1p = pow72f(q1[n]);
            Sf[n] = q1p * Sf[n] + g_sf[(((size_t)b * CH_ + cp) * NDIM_ + n) * DIM_ + d];
        }
    }
    for (int cp = CH_ - 1; cp > c; cp--) {
#pragma unroll
        for (int n = 0; n < NDIM_; n++) {
            float q2p = pow72f(q2[n]);
            Sb[n] = q2p * Sb[n] + g_sb[(((size_t)b * CH_ + cp) * NDIM_ + n) * DIM_ + d];
        }
    }
    int t0 = c * CL_;
    // descending pass: backward correction  c2 * q2^{CL-tl} * Sb
    float wv[NDIM_];
#pragma unroll
    for (int n = 0; n < NDIM_; n++) wv[n] = c2[n] * Sb[n] * q2[n];
    if (c < CH_ - 1) {
        for (int tl = CL_ - 1; tl >= 0; tl--) {
            size_t idx = (size_t)(t0 + tl + 1) * DIM_ + d;
            float y = yb[idx];
#pragma unroll
            for (int n = 0; n < NDIM_; n++) { y += wv[n]; wv[n] *= q2[n]; }
            yb[idx] = y;
        }
    }
    // ascending pass: forward correction c1 * q1^{tl+1} * Sf, + silu(y + x*omega)
    float sv[NDIM_];
#pragma unroll
    for (int n = 0; n < NDIM_; n++) sv[n] = c1[n] * Sf[n];
    float om = omega[d];
    for (int tl = 0; tl < CL_; tl++) {
        size_t idx = (size_t)(t0 + tl + 1) * DIM_ + d;
        float y = yb[idx];
#pragma unroll
        for (int n = 0; n < NDIM_; n++) { sv[n] *= q1[n]; y += sv[n]; }
        float u = y + xb[idx] * om;
        yb[idx] = u / (1.f + __expf(-u));
    }
}

// ================= tf32 mma GEMM: 128x128 CTA tile, 4 warps of 64x64 =================
__device__ __forceinline__ void gemm_tc_body(const float* __restrict__ A, const float* __restrict__ Bm,
                                             float* __restrict__ C, int M, int Nn,
                                             const float* __restrict__ bias, int bnb) {
    __shared__ float As[128][36];   // stride 36 (=4 mod 32): A-frag bank 4*gr+tg, distinct
    __shared__ float Bs[32][136];   // stride 136 (=8 mod 32): B-frag bank 8*tg+gr, distinct

    int tid = threadIdx.x, lane = tid & 31, w = tid >> 5;   // 4 warps
    int gr = lane >> 2, tg = lane & 3;
    int wm = w & 1, wn = w >> 1;
    int bm = blockIdx.y * 128, bn = bnb * 128;

    float acc[4][8][4];
#pragma unroll
    for (int mt = 0; mt < 4; mt++)
#pragma unroll
        for (int nt = 0; nt < 8; nt++)
#pragma unroll
            for (int e = 0; e < 4; e++) acc[mt][nt][e] = 0.f;

    for (int k0 = 0; k0 < 512; k0 += 32) {
#pragma unroll
        for (int it = 0; it < 8; it++) {     // A: 128x32, 8 float4/thread
            int idx = tid + it * 128;
            int row = idx >> 3, kq = (idx & 7) * 4;
            float4 v = make_float4(0.f, 0.f, 0.f, 0.f);
            if (bm + row < M) v = *(const float4*)(A + (size_t)(bm + row) * 512 + k0 + kq);
            As[row][kq + 0] = f2tff(v.x);
            As[row][kq + 1] = f2tff(v.y);
            As[row][kq + 2] = f2tff(v.z);
            As[row][kq + 3] = f2tff(v.w);
        }
#pragma unroll
        for (int it = 0; it < 8; it++) {     // B: 32x128, 8 float4/thread
            int idx = tid + it * 128;
            int kr = idx >> 5, nq = (idx & 31) * 4;
            float4 u = *(const float4*)(Bm + (size_t)(k0 + kr) * Nn + bn + nq);
            float4 ut = make_float4(f2tff(u.x), f2tff(u.y), f2tff(u.z), f2tff(u.w));
            *(float4*)(&Bs[kr][nq]) = ut;
        }
        __syncthreads();
#pragma unroll
        for (int kk = 0; kk < 4; kk++) {
            unsigned a[4][4];
#pragma unroll
            for (int mt = 0; mt < 4; mt++) {
                int r = wm * 64 + mt * 16 + gr;
                int cidx = kk * 8 + tg;
                a[mt][0] = __float_as_uint(As[r][cidx]);
                a[mt][1] = __float_as_uint(As[r + 8][cidx]);
                a[mt][2] = __float_as_uint(As[r][cidx + 4]);
                a[mt][3] = __float_as_uint(As[r + 8][cidx + 4]);
            }
            unsigned bf[8][2];
#pragma unroll
            for (int nt = 0; nt < 8; nt++) {
                int col = wn * 64 + nt * 8 + gr;
                bf[nt][0] = __float_as_uint(Bs[kk * 8 + tg][col]);
                bf[nt][1] = __float_as_uint(Bs[kk * 8 + tg + 4][col]);
            }
#pragma unroll
            for (int nt = 0; nt < 8; nt++)
#pragma unroll
                for (int mt = 0; mt < 4; mt++) mma8(acc[mt][nt], a[mt], bf[nt][0], bf[nt][1]);
        }
        __syncthreads();
    }
#pragma unroll
    for (int mt = 0; mt < 4; mt++) {
        int r0 = bm + wm * 64 + mt * 16 + gr;
#pragma unroll
        for (int nt = 0; nt < 8; nt++) {
            int col = bn + wn * 64 + nt * 8 + 2 * tg;
            float bx = bias ? bias[col] : 0.f, by = bias ? bias[col + 1] : 0.f;
            if (r0 < M)
                *(float2*)(C + (size_t)r0 * Nn + col) =
                    make_float2(acc[mt][nt][0] + bx, acc[mt][nt][1] + by);
            if (r0 + 8 < M)
                *(float2*)(C + (size_t)(r0 + 8) * Nn + col) =
                    make_float2(acc[mt][nt][2] + bx, acc[mt][nt][3] + by);
        }
    }
}

__global__ void __launch_bounds__(128, 2)
gemm_qkv_tc(const float* __restrict__ Wqk, const float* __restrict__ Wv) {
    if (blockIdx.x < 8)
        gemm_tc_body(g_xm, Wqk, g_qk, M_ROWS, 1024, nullptr, blockIdx.x);
    else
        gemm_tc_body(g_xm, Wv, g_v, M_ROWS, 512, nullptr, blockIdx.x - 8);
}
__global__ void __launch_bounds__(128, 2)
gemm_out_tc(const float* __restrict__ W, const float* __restrict__ bias,
            float* __restrict__ out) {
    gemm_tc_body(g_ao, W, out, M_ROWS, 512, bias, blockIdx.x);
}

// ================= Stage 3: flash attention, 96 q-rows/CTA, 6 warps =================
#define KSTR 68
#define VSTR 72
#define PSTR 68
#define QROWS 96
#define SMEM_FL (64 * KSTR + 64 * VSTR + QROWS * PSTR + (2 * N_ - 1))

__global__ void __launch_bounds__(192, 2) flash_attn_tc(const float* __restrict__ rb) {
    extern __shared__ float sm[];
    float* Ks  = sm;                       // [64][KSTR]
    float* Vs  = Ks + 64 * KSTR;           // [64][VSTR]
    float* Ps  = Vs + 64 * VSTR;           // [QROWS][PSTR]
    float* RBs = Ps + QROWS * PSTR;        // [1153]

    int b = blockIdx.z, h = blockIdx.y;
    int i0 = blockIdx.x * QROWS;
    int tid = threadIdx.x, lane = tid & 31, w = tid >> 5;
    int gr = lane >> 2, tg = lane & 3;

    const float* qb = g_qk + (size_t)b * N_ * 1024 + h * 64;
    const float* kb = qb + 512;
    const float* vb = g_v + (size_t)b * N_ * 512 + h * 64;

    for (int t = tid; t < 2 * N_ - 1; t += 192) RBs[t] = rb[t];

    unsigned qa[8][4];
    int rlo = i0 + w * 16 + gr;
    int rhi = rlo + 8;
#pragma unroll
    for (int kk = 0; kk < 8; kk++) {
        int c0 = kk * 8 + tg;
        float v0 = (rlo < N_) ? 0.125f * qb[(size_t)rlo * 1024 + c0]     : 0.f;
        float v1 = (rhi < N_) ? 0.125f * qb[(size_t)rhi * 1024 + c0]     : 0.f;
        float v2 = (rlo < N_) ? 0.125f * qb[(size_t)rlo * 1024 + c0 + 4] : 0.f;
        float v3 = (rhi < N_) ? 0.125f * qb[(size_t)rhi * 1024 + c0 + 4] : 0.f;
        qa[kk][0] = f2tf(v0); qa[kk][1] = f2tf(v1);
        qa[kk][2] = f2tf(v2); qa[kk][3] = f2tf(v3);
    }

    float o[8][4], ob[8][4];
#pragma unroll
    for (int nt = 0; nt < 8; nt++)
#pragma unroll
        for (int e = 0; e < 4; e++) { o[nt][e] = 0.f; ob[nt][e] = 0.f; }
    float mlo = -1e30f, mhi = -1e30f, zlo = 0.f, zhi = 0.f;

    for (int j0 = 0; j0 < N_; j0 += 64) {
        bool full = (j0 + 64 <= N_);
        __syncthreads();
        for (int idx = tid; idx < 1024; idx += 192) {
            int row = idx >> 4, cq = (idx & 15) * 4;
            int j = j0 + row;
            float4 kv = make_float4(0.f, 0.f, 0.f, 0.f);
            float4 vv = kv;
            if (full || j < N_) {
                kv = *(const float4*)(kb + (size_t)j * 1024 + cq);
                vv = *(const float4*)(vb + (size_t)j * 512 + cq);
            }
            float4 kt = make_float4(f2tff(kv.x), f2tff(kv.y), f2tff(kv.z), f2tff(kv.w));
            float4 vt = make_float4(f2tff(vv.x), f2tff(vv.y), f2tff(vv.z), f2tff(vv.w));
            *(float4*)(Ks + row * KSTR + cq) = kt;
            *(float4*)(Vs + row * VSTR + cq) = vt;
        }
        __syncthreads();

        // ---- S = Q @ K^T ----
        float s[8][4];
#pragma unroll
        for (int nt = 0; nt < 8; nt++) {
#pragma unroll
            for (int e = 0; e < 4; e++) s[nt][e] = 0.f;
#pragma unroll
            for (int kk = 0; kk < 8; kk++) {
                unsigned b0 = __float_as_uint(Ks[(nt * 8 + gr) * KSTR + kk * 8 + tg]);
                unsigned b1 = __float_as_uint(Ks[(nt * 8 + gr) * KSTR + kk * 8 + tg + 4]);
                mma8(s[nt], qa[kk], b0, b1);
            }
        }

        // ---- online softmax ----
        float tlo = -1e30f, thi = -1e30f;
#pragma unroll
        for (int nt = 0; nt < 8; nt++) {
            int col = j0 + nt * 8 + 2 * tg;
            if (full || col < N_)     { tlo = fmaxf(tlo, s[nt][0]); thi = fmaxf(thi, s[nt][2]); }
            if (full || col + 1 < N_) { tlo = fmaxf(tlo, s[nt][1]); thi = fmaxf(thi, s[nt][3]); }
        }
#pragma unroll
        for (int off = 1; off <= 2; off <<= 1) {
            tlo = fmaxf(tlo, __shfl_xor_sync(0xffffffffu, tlo, off));
            thi = fmaxf(thi, __shfl_xor_sync(0xffffffffu, thi, off));
        }
        float mlon = fmaxf(mlo, tlo), mhin = fmaxf(mhi, thi);
        float sclo = __expf(mlo - mlon), schi = __expf(mhi - mhin);
        float psl = 0.f, psh = 0.f;
        int prow_lo = (w * 16 + gr) * PSTR;
        int prow_hi = (w * 16 + gr + 8) * PSTR;
#pragma unroll
        for (int nt = 0; nt < 8; nt++) {
            int col = j0 + nt * 8 + 2 * tg;
            float p0 = (full || col     < N_) ? __expf(s[nt][0] - mlon) : 0.f;
            float p1 = (full || col + 1 < N_) ? __expf(s[nt][1] - mlon) : 0.f;
            float p2 = (full || col     < N_) ? __expf(s[nt][2] - mhin) : 0.f;
            float p3 = (full || col + 1 < N_) ? __expf(s[nt][3] - mhin) : 0.f;
            psl += p0 + p1; psh += p2 + p3;
            o[nt][0] *= sclo; o[nt][1] *= sclo;
            o[nt][2] *= schi; o[nt][3] *= schi;
            *(float2*)(Ps + prow_lo + nt * 8 + 2 * tg) = make_float2(f2tff(p0), f2tff(p1));
            *(float2*)(Ps + prow_hi + nt * 8 + 2 * tg) = make_float2(f2tff(p2), f2tff(p3));
        }
#pragma unroll
        for (int off = 1; off <= 2; off <<= 1) {
            psl += __shfl_xor_sync(0xffffffffu, psl, off);
            psh += __shfl_xor_sync(0xffffffffu, psh, off);
        }
        zlo = zlo * sclo + psl;  zhi = zhi * schi + psh;
        mlo = mlon;  mhi = mhin;
        __syncwarp();

        // ---- O += P @ V ;  Ob += bias @ V ----
#pragma unroll
        for (int kk = 0; kk < 8; kk++) {
            unsigned pa[4], ba[4];
            int pc = kk * 8 + tg;
            pa[0] = __float_as_uint(Ps[prow_lo + pc]);
            pa[1] = __float_as_uint(Ps[prow_hi + pc]);
            pa[2] = __float_as_uint(Ps[prow_lo + pc + 4]);
            pa[3] = __float_as_uint(Ps[prow_hi + pc + 4]);
            int jlo = j0 + kk * 8 + tg, jhi = jlo + 4;
            float b00 = (rlo < N_ && jlo < N_) ? RBs[576 + jlo - rlo] : 0.f;
            float b01 = (rhi < N_ && jlo < N_) ? RBs[576 + jlo - rhi] : 0.f;
            float b02 = (rlo < N_ && jhi < N_) ? RBs[576 + jhi - rlo] : 0.f;
            float b03 = (rhi < N_ && jhi < N_) ? RBs[576 + jhi - rhi] : 0.f;
            ba[0] = f2tf(b00); ba[1] = f2tf(b01); ba[2] = f2tf(b02); ba[3] = f2tf(b03);
#pragma unroll
            for (int nt = 0; nt < 8; nt++) {
                unsigned v0 = __float_as_uint(Vs[(kk * 8 + tg) * VSTR + nt * 8 + gr]);
                unsigned v1 = __float_as_uint(Vs[(kk * 8 + tg + 4) * VSTR + nt * 8 + gr]);
                mma8(o[nt],  pa, v0, v1);
                mma8(ob[nt], ba, v0, v1);
            }
        }
        __syncwarp();
    }

    // ---- epilogue ----
    float izlo = 1.f / zlo, izhi = 1.f / zhi;
#pragma unroll
    for (int nt = 0; nt < 8; nt++) {
        int col = h * 64 + nt * 8 + 2 * tg;
        if (rlo < N_) {
            float2 v = make_float2(o[nt][0] * izlo + ob[nt][0],
                                   o[nt][1] * izlo + ob[nt][1]);
            *(float2*)(g_ao + ((size_t)b * N_ + rlo) * 512 + col) = v;
        }
        if (rhi < N_) {
            float2 v = make_float2(o[nt][2] * izhi + ob[nt][2],
                                   o[nt][3] * izhi + ob[nt][3]);
            *(float2*)(g_ao + ((size_t)b * N_ + rhi) * 512 + col) = v;
        }
    }
}

// ================= launch =================
extern "C" void kernel_launch(void* const* d_in, const int* in_sizes, int n_in,
                              void* d_out, int out_size) {
    const float* x         = (const float*)d_in[0];
    const float* W_qk      = (const float*)d_in[1];
    const float* W_v       = (const float*)d_in[2];
    const float* W_out     = (const float*)d_in[3];
    const float* b_out     = (const float*)d_in[4];
    const float* rel_bias  = (const float*)d_in[5];
    const float* ema_delta = (const float*)d_in[6];
    const float* ema_alpha = (const float*)d_in[7];
    const float* ema_beta  = (const float*)d_in[8];
    const float* ema_gamma = (const float*)d_in[9];
    const float* ema_omega = (const float*)d_in[10];
    float* out = (float*)d_out;

    coef_kernel<<<(2 * DIM_ * NDIM_ + 255) / 256, 256>>>(ema_delta, ema_alpha, ema_beta, ema_gamma);
    ema1_kernel<<<dim3(DIM_ / 128, CH_, B_), 128>>>(x);
    ema2_kernel<<<dim3(DIM_ / 128, CH_, B_), 128>>>(x, ema_omega);

    gemm_qkv_tc<<<dim3(12, 145), 128>>>(W_qk, W_v);

    static int smem_set = 0;
    if (!smem_set) {
        cudaFuncSetAttribute(flash_attn_tc, cudaFuncAttributeMaxDynamicSharedMemorySize,
                             SMEM_FL * (int)sizeof(float));
        smem_set = 1;
    }
    flash_attn_tc<<<dim3((N_ + QROWS - 1) / QROWS, HEADS_, B_), 192,
                    SMEM_FL * sizeof(float)>>>(rel_bias);

    gemm_out_tc<<<dim3(4, 145), 128>>>(W_out, b_out, out);
}

// round 5
// speedup vs baseline: 10.0418x; 1.1770x over previous
#include <cuda_runtime.h>

#define B_     32
#define N_     577
#define L_     576
#define DIM_   512
#define HEADS_ 8
#define DH_    64
#define NDIM_  16
#define INNER_ 512
#define M_ROWS (B_ * N_)   // 18464
#define CH_    8           // EMA chunks
#define CL_    72          // EMA chunk length

// -------- scratch (device globals) --------
__device__ float g_xm[(size_t)B_ * N_ * DIM_];
__device__ float g_qk[(size_t)B_ * N_ * 2 * INNER_];
__device__ float g_v [(size_t)B_ * N_ * INNER_];
__device__ float g_ao[(size_t)B_ * N_ * INNER_];
__device__ float g_cq[NDIM_][2 * DIM_];
__device__ float g_cc[NDIM_][2 * DIM_];
__device__ float g_sf[(size_t)B_ * CH_ * NDIM_ * DIM_];
__device__ float g_sb[(size_t)B_ * CH_ * NDIM_ * DIM_];
__device__ float g_wqk[512 * 1024];
__device__ float g_wv [512 * 512];
__device__ float g_wo [512 * 512];

// ---------------- helpers ----------------
__device__ __forceinline__ unsigned f2tf(float x) {
    unsigned u;
    asm("cvt.rna.tf32.f32 %0, %1;" : "=r"(u) : "f"(x));
    return u;
}
__device__ __forceinline__ float f2tff(float x) { return __uint_as_float(f2tf(x)); }

__device__ __forceinline__ void mma8(float* c, const unsigned* a, unsigned b0, unsigned b1) {
    asm volatile(
        "mma.sync.aligned.m16n8k8.row.col.f32.tf32.tf32.f32 "
        "{%0,%1,%2,%3},{%4,%5,%6,%7},{%8,%9},{%0,%1,%2,%3};"
        : "+f"(c[0]), "+f"(c[1]), "+f"(c[2]), "+f"(c[3])
        : "r"(a[0]), "r"(a[1]), "r"(a[2]), "r"(a[3]), "r"(b0), "r"(b1));
}

__device__ __forceinline__ unsigned s2u(const void* p) {
    return (unsigned)__cvta_generic_to_shared(p);
}
__device__ __forceinline__ void cp16(unsigned dst, const void* src, int srcsz) {
    asm volatile("cp.async.cg.shared.global [%0], [%1], 16, %2;"
                 :: "r"(dst), "l"(src), "r"(srcsz));
}
#define CP_COMMIT() asm volatile("cp.async.commit_group;")
#define CP_WAIT1()  asm volatile("cp.async.wait_group 1;")

// ================= Stage 0: EMA coefficients + weight rounding =================
__global__ void coef_kernel(const float* __restrict__ delta, const float* __restrict__ alpha,
                            const float* __restrict__ beta,  const float* __restrict__ gamma) {
    int idx = blockIdx.x * blockDim.x + threadIdx.x;
    if (idx >= 2 * DIM_ * NDIM_) return;
    int d = idx / NDIM_;
    int n = idx % NDIM_;
    float p  = 1.f / (1.f + expf(-delta[idx]));
    float sa = 1.f / (1.f + expf(-alpha[idx]));
    g_cq[n][d] = 1.f - p * sa;
    g_cc[n][d] = p * beta[idx] * gamma[idx] * 0.25f;
}

__global__ void wcvt_kernel(const float* __restrict__ wqk, const float* __restrict__ wv,
                            const float* __restrict__ wo) {
    int i = blockIdx.x * 256 + threadIdx.x;
    if (i < 512 * 1024) g_wqk[i] = f2tff(wqk[i]);
    if (i < 512 * 512) {
        g_wv[i] = f2tff(wv[i]);
        g_wo[i] = f2tff(wo[i]);
    }
}

// ================= Stage 1a: chunk-local EMA scans =================
__global__ void ema1_kernel(const float* __restrict__ x) {
    int d = blockIdx.x * 128 + threadIdx.x;
    int c = blockIdx.y, b = blockIdx.z;
    const float* xb = x    + (size_t)b * N_ * DIM_;
    float*       yb = g_xm + (size_t)b * N_ * DIM_;
    if (c == 0) yb[d] = f2tff(xb[d]);   // cls passthrough (rounded: feeds GEMM A)

    float q1[NDIM_], c1[NDIM_], q2[NDIM_], c2[NDIM_], s[NDIM_];
#pragma unroll
    for (int n = 0; n < NDIM_; n++) {
        q1[n] = g_cq[n][d];         c1[n] = g_cc[n][d];
        q2[n] = g_cq[n][d + DIM_];  c2[n] = g_cc[n][d + DIM_];
        s[n] = 0.f;
    }
    int t0 = c * CL_;
    for (int tl = 0; tl < CL_; tl++) {
        size_t idx = (size_t)(t0 + tl + 1) * DIM_ + d;
        float xv = xb[idx];
        float y = 0.f;
#pragma unroll
        for (int n = 0; n < NDIM_; n++) { s[n] = q1[n] * s[n] + xv; y += c1[n] * s[n]; }
        yb[idx] = y;
    }
#pragma unroll
    for (int n = 0; n < NDIM_; n++) {
        g_sf[(((size_t)b * CH_ + c) * NDIM_ + n) * DIM_ + d] = s[n];
        s[n] = 0.f;
    }
    for (int tl = CL_ - 1; tl >= 0; tl--) {
        size_t idx = (size_t)(t0 + tl + 1) * DIM_ + d;
        float xv = xb[idx];
        float y = yb[idx];
#pragma unroll
        for (int n = 0; n < NDIM_; n++) { s[n] = q2[n] * s[n] + xv; y += c2[n] * s[n]; }
        yb[idx] = y;
    }
#pragma unroll
    for (int n = 0; n < NDIM_; n++)
        g_sb[(((size_t)b * CH_ + c) * NDIM_ + n) * DIM_ + d] = s[n];
}

// ================= Stage 1b: cross-chunk corrections + silu =================
__device__ __forceinline__ float pow72f(float q) {
    float q2 = q * q, q4 = q2 * q2, q8 = q4 * q4;
    float q9 = q8 * q, q18 = q9 * q9, q36 = q18 * q18;
    return q36 * q36;
}
__global__ void ema2_kernel(const float* __restrict__ x, const float* __restrict__ omega) {
    int d = blockIdx.x * 128 + threadIdx.x;
    int c = blockIdx.y, b = blockIdx.z;
    const float* xb = x    + (size_t)b * N_ * DIM_;
    float*       yb = g_xm + (size_t)b * N_ * DIM_;

    float q1[NDIM_], c1[NDIM_], q2[NDIM_], c2[NDIM_];
#pragma unroll
    for (int n = 0; n < NDIM_; n++) {
        q1[n] = g_cq[n][d];         c1[n] = g_cc[n][d];
        q2[n] = g_cq[n][d + DIM_];  c2[n] = g_cc[n][d + DIM_];
    }
    float Sf[NDIM_], Sb[NDIM_];
#pragma unroll
    for (int n = 0; n < NDIM_; n++) { Sf[n] = 0.f; Sb[n] = 0.f; }
    for (int cp = 0; cp < c; cp++) {
#pragma unroll
        for (int n = 0; n < NDIM_; n++) {
            float q1p = pow72f(q1[n]);
            Sf[n] = q1p * Sf[n] + g_sf[(((size_t)b * CH_ + cp) * NDIM_ + n) * DIM_ + d];
        }
    }
    for (int cp = CH_ - 1; cp > c; cp--) {
#pragma unroll
        for (int n = 0; n < NDIM_; n++) {
            float q2p = pow72f(q2[n]);
            Sb[n] = q2p * Sb[n] + g_sb[(((size_t)b * CH_ + cp) * NDIM_ + n) * DIM_ + d];
        }
    }
    int t0 = c * CL_;
    float wv[NDIM_];
#pragma unroll
    for (int n = 0; n < NDIM_; n++) wv[n] = c2[n] * Sb[n] * q2[n];
    if (c < CH_ - 1) {
        for (int tl = CL_ - 1; tl >= 0; tl--) {
            size_t idx = (size_t)(t0 + tl + 1) * DIM_ + d;
            float y = yb[idx];
#pragma unroll
            for (int n = 0; n < NDIM_; n++) { y += wv[n]; wv[n] *= q2[n]; }
            yb[idx] = y;
        }
    }
    float sv[NDIM_];
#pragma unroll
    for (int n = 0; n < NDIM_; n++) sv[n] = c1[n] * Sf[n];
    float om = omega[d];
    for (int tl = 0; tl < CL_; tl++) {
        size_t idx = (size_t)(t0 + tl + 1) * DIM_ + d;
        float y = yb[idx];
#pragma unroll
        for (int n = 0; n < NDIM_; n++) { sv[n] *= q1[n]; y += sv[n]; }
        float u = y + xb[idx] * om;
        yb[idx] = f2tff(u / (1.f + __expf(-u)));   // rounded: feeds GEMM A
    }
}

// ================= tf32 GEMM: 128x128 CTA, 4 warps 64x64, cp.async 3-stage =================
#define ASLAB (128 * 36)
#define BSLAB (32 * 136)
#define GSMEM_BYTES (3 * (ASLAB + BSLAB) * 4)

__device__ __forceinline__ void gemm_tc_body(const float* __restrict__ A, const float* __restrict__ Bm,
                                             float* __restrict__ C, int M, int Nn,
                                             const float* __restrict__ bias, int bnb, bool rnd) {
    extern __shared__ float gsm[];
    float* As = gsm;
    float* Bs = gsm + 3 * ASLAB;
    unsigned as_u = s2u(As), bs_u = s2u(Bs);

    int tid = threadIdx.x, lane = tid & 31, w = tid >> 5;
    int gr = lane >> 2, tg = lane & 3;
    int wm = w & 1, wn = w >> 1;
    int bm = blockIdx.y * 128, bn = bnb * 128;

    // slab issue: stage s covers k = s*32 .. s*32+31
#define GEMM_ISSUE(s)                                                                  \
    do {                                                                               \
        int _buf = (s) % 3, _k0 = (s) * 32;                                            \
        unsigned _ad = as_u + (unsigned)(_buf * ASLAB * 4);                            \
        unsigned _bd = bs_u + (unsigned)(_buf * BSLAB * 4);                            \
        _Pragma("unroll")                                                              \
        for (int it = 0; it < 8; it++) {                                               \
            int idx = tid + it * 128;                                                  \
            int row = idx >> 3, kq = (idx & 7) * 4;                                    \
            bool ok = (bm + row < M);                                                  \
            const float* src = A + (size_t)(ok ? bm + row : 0) * 512 + _k0 + kq;       \
            cp16(_ad + (unsigned)((row * 36 + kq) * 4), src, ok ? 16 : 0);             \
        }                                                                              \
        _Pragma("unroll")                                                              \
        for (int it = 0; it < 8; it++) {                                               \
            int idx = tid + it * 128;                                                  \
            int kr = idx >> 5, nq = (idx & 31) * 4;                                    \
            cp16(_bd + (unsigned)((kr * 136 + nq) * 4),                                \
                 Bm + (size_t)(_k0 + kr) * Nn + bn + nq, 16);                          \
        }                                                                              \
    } while (0)

    GEMM_ISSUE(0); CP_COMMIT();
    GEMM_ISSUE(1); CP_COMMIT();

    float acc[4][8][4];
#pragma unroll
    for (int mt = 0; mt < 4; mt++)
#pragma unroll
        for (int nt = 0; nt < 8; nt++)
#pragma unroll
            for (int e = 0; e < 4; e++) acc[mt][nt][e] = 0.f;

    for (int s = 0; s < 16; s++) {
        CP_WAIT1();
        __syncthreads();
        if (s + 2 < 16) GEMM_ISSUE(s + 2);
        CP_COMMIT();
        const float* Ab = As + (s % 3) * ASLAB;
        const float* Bb = Bs + (s % 3) * BSLAB;
#pragma unroll
        for (int kk = 0; kk < 4; kk++) {
            unsigned a[4][4];
#pragma unroll
            for (int mt = 0; mt < 4; mt++) {
                int r = wm * 64 + mt * 16 + gr;
                int cidx = kk * 8 + tg;
                a[mt][0] = __float_as_uint(Ab[r * 36 + cidx]);
                a[mt][1] = __float_as_uint(Ab[(r + 8) * 36 + cidx]);
                a[mt][2] = __float_as_uint(Ab[r * 36 + cidx + 4]);
                a[mt][3] = __float_as_uint(Ab[(r + 8) * 36 + cidx + 4]);
            }
            unsigned bf[8][2];
#pragma unroll
            for (int nt = 0; nt < 8; nt++) {
                int col = wn * 64 + nt * 8 + gr;
                bf[nt][0] = __float_as_uint(Bb[(kk * 8 + tg) * 136 + col]);
                bf[nt][1] = __float_as_uint(Bb[(kk * 8 + tg + 4) * 136 + col]);
            }
#pragma unroll
            for (int nt = 0; nt < 8; nt++)
#pragma unroll
                for (int mt = 0; mt < 4; mt++) mma8(acc[mt][nt], a[mt], bf[nt][0], bf[nt][1]);
        }
    }
#pragma unroll
    for (int mt = 0; mt < 4; mt++) {
        int r0 = bm + wm * 64 + mt * 16 + gr;
#pragma unroll
        for (int nt = 0; nt < 8; nt++) {
            int col = bn + wn * 64 + nt * 8 + 2 * tg;
            float bx = bias ? bias[col] : 0.f, by = bias ? bias[col + 1] : 0.f;
            float e0 = acc[mt][nt][0] + bx, e1 = acc[mt][nt][1] + by;
            float e2 = acc[mt][nt][2] + bx, e3 = acc[mt][nt][3] + by;
            if (rnd) { e0 = f2tff(e0); e1 = f2tff(e1); e2 = f2tff(e2); e3 = f2tff(e3); }
            if (r0 < M)     *(float2*)(C + (size_t)r0 * Nn + col)       = make_float2(e0, e1);
            if (r0 + 8 < M) *(float2*)(C + (size_t)(r0 + 8) * Nn + col) = make_float2(e2, e3);
        }
    }
#undef GEMM_ISSUE
}

__global__ void __launch_bounds__(128)
gemm_qkv_tc() {
    if (blockIdx.x < 8)
        gemm_tc_body(g_xm, g_wqk, g_qk, M_ROWS, 1024, nullptr, blockIdx.x, true);
    else
        gemm_tc_body(g_xm, g_wv, g_v, M_ROWS, 512, nullptr, blockIdx.x - 8, true);
}
__global__ void __launch_bounds__(128)
gemm_out_tc(const float* __restrict__ bias, float* __restrict__ out) {
    gemm_tc_body(g_ao, g_wo, out, M_ROWS, 512, bias, blockIdx.x, false);
}

// ================= Stage 3: flash attention, cp.async 2-stage K/V =================
#define KSTR 68
#define VSTR 72
#define PSTR 68
#define QROWS 96
#define KBUF (64 * KSTR)
#define VBUF (64 * VSTR)
#define NT_ ((N_ + 63) / 64)    // 10
#define FSMEM_FLOATS (2 * KBUF + 2 * VBUF + QROWS * PSTR + (2 * N_ - 1))

__global__ void __launch_bounds__(192, 2) flash_attn_tc(const float* __restrict__ rb) {
    extern __shared__ float sm[];
    float* Ks  = sm;                           // [2][64][KSTR]
    float* Vs  = sm + 2 * KBUF;                // [2][64][VSTR]
    float* Ps  = sm + 2 * KBUF + 2 * VBUF;     // [QROWS][PSTR]
    float* RBs = Ps + QROWS * PSTR;            // [1153]
    unsigned ks_u = s2u(Ks), vs_u = s2u(Vs);

    int b = blockIdx.z, h = blockIdx.y;
    int i0 = blockIdx.x * QROWS;
    int tid = threadIdx.x, lane = tid & 31, w = tid >> 5;
    int gr = lane >> 2, tg = lane & 3;

    const float* qb = g_qk + (size_t)b * N_ * 1024 + h * 64;
    const float* kb = qb + 512;
    const float* vb = g_v + (size_t)b * N_ * 512 + h * 64;

    for (int t = tid; t < 2 * N_ - 1; t += 192) RBs[t] = rb[t];

#define FL_ISSUE(jt)                                                                   \
    do {                                                                               \
        int _buf = (jt) & 1, _j0 = (jt) * 64;                                          \
        unsigned _kd = ks_u + (unsigned)(_buf * KBUF * 4);                             \
        unsigned _vd = vs_u + (unsigned)(_buf * VBUF * 4);                             \
        for (int idx = tid; idx < 1024; idx += 192) {                                  \
            int row = idx >> 4, cq = (idx & 15) * 4;                                   \
            int j = _j0 + row;                                                         \
            bool ok = (j < N_);                                                        \
            int js = ok ? j : 0;                                                       \
            cp16(_kd + (unsigned)((row * KSTR + cq) * 4),                              \
                 kb + (size_t)js * 1024 + cq, ok ? 16 : 0);                            \
            cp16(_vd + (unsigned)((row * VSTR + cq) * 4),                              \
                 vb + (size_t)js * 512 + cq, ok ? 16 : 0);                             \
        }                                                                              \
    } while (0)

    // Q fragments (pre-rounded tf32 in g_qk; x0.125 is exact)
    unsigned qa[8][4];
    int rlo = i0 + w * 16 + gr;
    int rhi = rlo + 8;
#pragma unroll
    for (int kk = 0; kk < 8; kk++) {
        int c0 = kk * 8 + tg;
        float v0 = (rlo < N_) ? 0.125f * qb[(size_t)rlo * 1024 + c0]     : 0.f;
        float v1 = (rhi < N_) ? 0.125f * qb[(size_t)rhi * 1024 + c0]     : 0.f;
        float v2 = (rlo < N_) ? 0.125f * qb[(size_t)rlo * 1024 + c0 + 4] : 0.f;
        float v3 = (rhi < N_) ? 0.125f * qb[(size_t)rhi * 1024 + c0 + 4] : 0.f;
        qa[kk][0] = __float_as_uint(v0); qa[kk][1] = __float_as_uint(v1);
        qa[kk][2] = __float_as_uint(v2); qa[kk][3] = __float_as_uint(v3);
    }

    FL_ISSUE(0); CP_COMMIT();

    float o[8][4], ob[8][4];
#pragma unroll
    for (int nt = 0; nt < 8; nt++)
#pragma unroll
        for (int e = 0; e < 4; e++) { o[nt][e] = 0.f; ob[nt][e] = 0.f; }
    float mlo = -1e30f, mhi = -1e30f, zlo = 0.f, zhi = 0.f;

    for (int jt = 0; jt < NT_; jt++) {
        int j0 = jt * 64;
        bool full = (j0 + 64 <= N_);
        __syncthreads();                       // prior compute done: other buffer free
        if (jt + 1 < NT_) FL_ISSUE(jt + 1);
        CP_COMMIT();
        CP_WAIT1();                            // tile jt arrived
        __syncthreads();
        const float* Ksb = Ks + (jt & 1) * KBUF;
        const float* Vsb = Vs + (jt & 1) * VBUF;

        // ---- S = Q @ K^T ----
        float s[8][4];
#pragma unroll
        for (int nt = 0; nt < 8; nt++) {
#pragma unroll
            for (int e = 0; e < 4; e++) s[nt][e] = 0.f;
#pragma unroll
            for (int kk = 0; kk < 8; kk++) {
                unsigned b0 = __float_as_uint(Ksb[(nt * 8 + gr) * KSTR + kk * 8 + tg]);
                unsigned b1 = __float_as_uint(Ksb[(nt * 8 + gr) * KSTR + kk * 8 + tg + 4]);
                mma8(s[nt], qa[kk], b0, b1);
            }
        }

        // ---- online softmax ----
        float tlo = -1e30f, thi = -1e30f;
#pragma unroll
        for (int nt = 0; nt < 8; nt++) {
            int col = j0 + nt * 8 + 2 * tg;
            if (full || col < N_)     { tlo = fmaxf(tlo, s[nt][0]); thi = fmaxf(thi, s[nt][2]); }
            if (full || col + 1 < N_) { tlo = fmaxf(tlo, s[nt][1]); thi = fmaxf(thi, s[nt][3]); }
        }
#pragma unroll
        for (int off = 1; off <= 2; off <<= 1) {
            tlo = fmaxf(tlo, __shfl_xor_sync(0xffffffffu, tlo, off));
            thi = fmaxf(thi, __shfl_xor_sync(0xffffffffu, thi, off));
        }
        float mlon = fmaxf(mlo, tlo), mhin = fmaxf(mhi, thi);
        float sclo = __expf(mlo - mlon), schi = __expf(mhi - mhin);
        float psl = 0.f, psh = 0.f;
        int prow_lo = (w * 16 + gr) * PSTR;
        int prow_hi = (w * 16 + gr + 8) * PSTR;
#pragma unroll
        for (int nt = 0; nt < 8; nt++) {
            int col = j0 + nt * 8 + 2 * tg;
            float p0 = (full || col     < N_) ? __expf(s[nt][0] - mlon) : 0.f;
            float p1 = (full || col + 1 < N_) ? __expf(s[nt][1] - mlon) : 0.f;
            float p2 = (full || col     < N_) ? __expf(s[nt][2] - mhin) : 0.f;
            float p3 = (full || col + 1 < N_) ? __expf(s[nt][3] - mhin) : 0.f;
            psl += p0 + p1; psh += p2 + p3;
            o[nt][0] *= sclo; o[nt][1] *= sclo;
            o[nt][2] *= schi; o[nt][3] *= schi;
            *(float2*)(Ps + prow_lo + nt * 8 + 2 * tg) = make_float2(f2tff(p0), f2tff(p1));
            *(float2*)(Ps + prow_hi + nt * 8 + 2 * tg) = make_float2(f2tff(p2), f2tff(p3));
        }
#pragma unroll
        for (int off = 1; off <= 2; off <<= 1) {
            psl += __shfl_xor_sync(0xffffffffu, psl, off);
            psh += __shfl_xor_sync(0xffffffffu, psh, off);
        }
        zlo = zlo * sclo + psl;  zhi = zhi * schi + psh;
        mlo = mlon;  mhi = mhin;
        __syncwarp();

        // ---- O += P @ V ;  Ob += bias @ V ----
#pragma unroll
        for (int kk = 0; kk < 8; kk++) {
            unsigned pa[4], ba[4];
            int pc = kk * 8 + tg;
            pa[0] = __float_as_uint(Ps[prow_lo + pc]);
            pa[1] = __float_as_uint(Ps[prow_hi + pc]);
            pa[2] = __float_as_uint(Ps[prow_lo + pc + 4]);
            pa[3] = __float_as_uint(Ps[prow_hi + pc + 4]);
            int jlo = j0 + kk * 8 + tg, jhi = jlo + 4;
            float b00 = (rlo < N_ && jlo < N_) ? RBs[576 + jlo - rlo] : 0.f;
            float b01 = (rhi < N_ && jlo < N_) ? RBs[576 + jlo - rhi] : 0.f;
            float b02 = (rlo < N_ && jhi < N_) ? RBs[576 + jhi - rlo] : 0.f;
            float b03 = (rhi < N_ && jhi < N_) ? RBs[576 + jhi - rhi] : 0.f;
            ba[0] = f2tf(b00); ba[1] = f2tf(b01); ba[2] = f2tf(b02); ba[3] = f2tf(b03);
#pragma unroll
            for (int nt = 0; nt < 8; nt++) {
                unsigned v0 = __float_as_uint(Vsb[(kk * 8 + tg) * VSTR + nt * 8 + gr]);
                unsigned v1 = __float_as_uint(Vsb[(kk * 8 + tg + 4) * VSTR + nt * 8 + gr]);
                mma8(o[nt],  pa, v0, v1);
                mma8(ob[nt], ba, v0, v1);
            }
        }
        __syncwarp();
    }

    // ---- epilogue: round for W_out GEMM A-operand ----
    float izlo = 1.f / zlo, izhi = 1.f / zhi;
#pragma unroll
    for (int nt = 0; nt < 8; nt++) {
        int col = h * 64 + nt * 8 + 2 * tg;
        if (rlo < N_) {
            float2 v = make_float2(f2tff(o[nt][0] * izlo + ob[nt][0]),
                                   f2tff(o[nt][1] * izlo + ob[nt][1]));
            *(float2*)(g_ao + ((size_t)b * N_ + rlo) * 512 + col) = v;
        }
        if (rhi < N_) {
            float2 v = make_float2(f2tff(o[nt][2] * izhi + ob[nt][2]),
                                   f2tff(o[nt][3] * izhi + ob[nt][3]));
            *(float2*)(g_ao + ((size_t)b * N_ + rhi) * 512 + col) = v;
        }
    }
#undef FL_ISSUE
}

// ================= launch =================
extern "C" void kernel_launch(void* const* d_in, const int* in_sizes, int n_in,
                              void* d_out, int out_size) {
    const float* x         = (const float*)d_in[0];
    const float* W_qk      = (const float*)d_in[1];
    const float* W_v       = (const float*)d_in[2];
    const float* W_out     = (const float*)d_in[3];
    const float* b_out     = (const float*)d_in[4];
    const float* rel_bias  = (const float*)d_in[5];
    const float* ema_delta = (const float*)d_in[6];
    const float* ema_alpha = (const float*)d_in[7];
    const float* ema_beta  = (const float*)d_in[8];
    const float* ema_gamma = (const float*)d_in[9];
    const float* ema_omega = (const float*)d_in[10];
    float* out = (float*)d_out;

    static int attr_set = 0;
    if (!attr_set) {
        cudaFuncSetAttribute(gemm_qkv_tc, cudaFuncAttributeMaxDynamicSharedMemorySize, GSMEM_BYTES);
        cudaFuncSetAttribute(gemm_out_tc, cudaFuncAttributeMaxDynamicSharedMemorySize, GSMEM_BYTES);
        cudaFuncSetAttribute(flash_attn_tc, cudaFuncAttributeMaxDynamicSharedMemorySize,
                             FSMEM_FLOATS * (int)sizeof(float));
        attr_set = 1;
    }

    coef_kernel<<<(2 * DIM_ * NDIM_ + 255) / 256, 256>>>(ema_delta, ema_alpha, ema_beta, ema_gamma);
    wcvt_kernel<<<(512 * 1024 + 255) / 256, 256>>>(W_qk, W_v, W_out);
    ema1_kernel<<<dim3(DIM_ / 128, CH_, B_), 128>>>(x);
    ema2_kernel<<<dim3(DIM_ / 128, CH_, B_), 128>>>(x, ema_omega);

    gemm_qkv_tc<<<dim3(12, 145), 128, GSMEM_BYTES>>>();

    flash_attn_tc<<<dim3((N_ + QROWS - 1) / QROWS, HEADS_, B_), 192,
                    FSMEM_FLOATS * sizeof(float)>>>(rel_bias);

    gemm_out_tc<<<dim3(4, 145), 128, GSMEM_BYTES>>>(b_out, out);
}